// round 12
// baseline (speedup 1.0000x reference)
#include <cuda_runtime.h>
#include <cuda_fp16.h>
#include <cuda_fp8.h>
#include <mma.h>

using namespace nvcuda;

#define NN 100000
#define NE 1600000
#define NG 512

// ---------------- scratch (device globals; no allocations allowed) ----------
__device__ int    g_cnti[NN];         // int in-degree counts (deg = cnti + 1)
__device__ int    g_rowstart[NN + 1]; // CSR row offsets
__device__ int    g_cursor[NN];       // CSR fill cursors (init = rowstart)
__device__ float2 g_csr[NE];          // per-edge (norm, src-as-int)
__device__ float  g_dinv[NN];         // rsqrt(deg)
__device__ float  g_inv[NN];          // 1/deg
__device__ uint4  g_x16v[NN * 10];    // x as __half[NN*80] (cols 78,79 = 0)
__device__ uint4  g_agg1v[NN * 10];   // aggregated x as __half[NN*80]
__device__ uint2  g_h1qv[NN * 16];    // relu(gcn1) as fp8 e4m3 [NN*128]
__device__ uint4  g_agg2v[NN * 16];   // aggregated h1 as __half[NN*128]
__device__ __half g_w1h[80 * 128];    // W1 as f16, K padded to 80
__device__ __half g_w2h[128 * 256];   // W2 as f16
__device__ __half g_fc1h[320 * 512];  // fc1_w as f16
__device__ __half g_fc2h[512];        // fc2_w as f16
__device__ float  g_sums[NG * 256];   // per-graph sums of h2
__device__ float  g_cnt[NG];          // per-graph node counts
__device__ float  g_ptab[25 * 8 * 64];// precomputed emb@conv_w table [tok][k][o]
__device__ float  g_prot[NG * 64];    // protein features after maxpool

// f16x8 reduction helper: p += v * nh (elementwise, 8 halves)
__device__ __forceinline__ void red_f16x8(__half* p, uint4 v, __half2 nh) {
    __half2 h0 = __hmul2(*(const __half2*)&v.x, nh);
    __half2 h1 = __hmul2(*(const __half2*)&v.y, nh);
    __half2 h2 = __hmul2(*(const __half2*)&v.z, nh);
    __half2 h3 = __hmul2(*(const __half2*)&v.w, nh);
    asm volatile("red.global.add.noftz.v4.f16x2 [%0], {%1,%2,%3,%4};"
                 :: "l"(p),
                    "r"(*(const unsigned int*)&h0), "r"(*(const unsigned int*)&h1),
                    "r"(*(const unsigned int*)&h2), "r"(*(const unsigned int*)&h3)
                 : "memory");
}

// 8 fp8(e4m3) packed in uint2 -> 8 floats
__device__ __forceinline__ void fp8x8_to_f32x8(uint2 qv, float* f) {
    __half2_raw a0 = __nv_cvt_fp8x2_to_halfraw2(
        (__nv_fp8x2_storage_t)(qv.x & 0xFFFF), __NV_E4M3);
    __half2_raw a1 = __nv_cvt_fp8x2_to_halfraw2(
        (__nv_fp8x2_storage_t)(qv.x >> 16), __NV_E4M3);
    __half2_raw a2 = __nv_cvt_fp8x2_to_halfraw2(
        (__nv_fp8x2_storage_t)(qv.y & 0xFFFF), __NV_E4M3);
    __half2_raw a3 = __nv_cvt_fp8x2_to_halfraw2(
        (__nv_fp8x2_storage_t)(qv.y >> 16), __NV_E4M3);
    float2 b0 = __half22float2(*(__half2*)&a0);
    float2 b1 = __half22float2(*(__half2*)&a1);
    float2 b2 = __half22float2(*(__half2*)&a2);
    float2 b3 = __half22float2(*(__half2*)&a3);
    f[0] = b0.x; f[1] = b0.y; f[2] = b1.x; f[3] = b1.y;
    f[4] = b2.x; f[5] = b2.y; f[6] = b3.x; f[7] = b3.y;
}

// ---------------- zero + degree count ----------------------------------------
__global__ void k_zero() {
    int t = blockIdx.x * blockDim.x + threadIdx.x;
    int stride = gridDim.x * blockDim.x;
    for (int i = t; i < NN; i += stride) g_cnti[i] = 0;
    for (int i = t; i < NG * 256; i += stride) g_sums[i] = 0.f;
    for (int i = t; i < NG; i += stride) g_cnt[i] = 0.f;
}

__global__ void k_deg(const int* __restrict__ dst) {
    int t = blockIdx.x * blockDim.x + threadIdx.x;
    if (t < NE) atomicAdd(&g_cnti[dst[t]], 1);
}

// init: x16 = f16(x) zero-padded to 80; agg1 = f16(x/deg); dinv/inv per node;
// also the per-graph node count.
__global__ void k_init1(const float* __restrict__ x,
                        const int* __restrict__ batch) {
    int t = blockIdx.x * blockDim.x + threadIdx.x;
    if (t < NN * 10) {
        int i = t / 10;
        int q = t - i * 10;
        float d = (float)g_cnti[i] + 1.0f;
        float inv = 1.0f / d;
        if (q == 0) {
            g_dinv[i] = rsqrtf(d);
            g_inv[i] = inv;
            atomicAdd(&g_cnt[batch[i]], 1.0f);
        }
        float v[8];
        if (q < 9) {
            const float2* xp = (const float2*)(x + (long)i * 78 + q * 8);
#pragma unroll
            for (int j = 0; j < 4; j++) {
                float2 a = xp[j];
                v[2 * j] = a.x; v[2 * j + 1] = a.y;
            }
        } else {
            const float2* xp = (const float2*)(x + (long)i * 78 + 72);
#pragma unroll
            for (int j = 0; j < 3; j++) {
                float2 a = xp[j];
                v[2 * j] = a.x; v[2 * j + 1] = a.y;
            }
            v[6] = 0.f; v[7] = 0.f;
        }
        uint4 raw, agg;
        __half2* rp = (__half2*)&raw;
        __half2* ap = (__half2*)&agg;
#pragma unroll
        for (int j = 0; j < 4; j++) {
            rp[j] = __floats2half2_rn(v[2 * j], v[2 * j + 1]);
            ap[j] = __floats2half2_rn(v[2 * j] * inv, v[2 * j + 1] * inv);
        }
        g_x16v[(long)i * 10 + q] = raw;
        g_agg1v[(long)i * 10 + q] = agg;
    }
}

// ---------------- edge scatter, layer 1 (f16, flat chunk space) -------------
__global__ void k_scatter1(const int* __restrict__ src,
                           const int* __restrict__ dst) {
    const int W = 2048 * 8;                 // total warps
    const int EPW = (NE + W - 1) / W;       // 98 edges per warp
    int w = (blockIdx.x * blockDim.x + threadIdx.x) >> 5;
    int lane = threadIdx.x & 31;
    int e0 = w * EPW;
    if (e0 >= NE) return;
    int ecnt = min(EPW, NE - e0);
    int nchunk = ecnt * 10;
    __half* agg = (__half*)g_agg1v;

    int c = lane;
    for (; c + 32 < nchunk; c += 64) {
        int c0 = c, c1 = c + 32;
        int le0 = c0 / 10, q0 = c0 - le0 * 10;
        int le1 = c1 / 10, q1 = c1 - le1 * 10;
        int e0i = e0 + le0, e1i = e0 + le1;
        int s0 = __ldg(src + e0i), d0 = __ldg(dst + e0i);
        int s1 = __ldg(src + e1i), d1 = __ldg(dst + e1i);
        float n0 = __ldg(g_dinv + s0) * __ldg(g_dinv + d0);
        float n1 = __ldg(g_dinv + s1) * __ldg(g_dinv + d1);
        uint4 v0 = g_x16v[(long)s0 * 10 + q0];
        uint4 v1 = g_x16v[(long)s1 * 10 + q1];
        red_f16x8(agg + (long)d0 * 80 + q0 * 8, v0, __float2half2_rn(n0));
        red_f16x8(agg + (long)d1 * 80 + q1 * 8, v1, __float2half2_rn(n1));
    }
    for (; c < nchunk; c += 32) {
        int le = c / 10, q = c - le * 10;
        int e = e0 + le;
        int s = __ldg(src + e), d = __ldg(dst + e);
        float nrm = __ldg(g_dinv + s) * __ldg(g_dinv + d);
        uint4 v = g_x16v[(long)s * 10 + q];
        red_f16x8(agg + (long)d * 80 + q * 8, v, __float2half2_rn(nrm));
    }
}

// ---------------- CSR build: scan + fill -------------------------------------
__global__ __launch_bounds__(1024) void k_scan() {
    __shared__ int ssum[1024];
    const int CH = (NN + 1023) / 1024;   // 98
    int t = threadIdx.x;
    int base = t * CH;
    int sum = 0;
    for (int i = 0; i < CH; i++) {
        int j = base + i;
        if (j < NN) sum += g_cnti[j];
    }
    ssum[t] = sum;
    __syncthreads();
    for (int off = 1; off < 1024; off <<= 1) {
        int v = (t >= off) ? ssum[t - off] : 0;
        __syncthreads();
        ssum[t] += v;
        __syncthreads();
    }
    int run = ssum[t] - sum;             // exclusive prefix
    for (int i = 0; i < CH; i++) {
        int j = base + i;
        if (j < NN) {
            g_rowstart[j] = run;
            g_cursor[j] = run;
            run += g_cnti[j];
        }
    }
    if (t == 1023) g_rowstart[NN] = run;
}

__global__ void k_fill(const int* __restrict__ src, const int* __restrict__ dst) {
    int t = blockIdx.x * blockDim.x + threadIdx.x;
    if (t < NE) {
        int s = src[t], d = dst[t];
        int pos = atomicAdd(&g_cursor[d], 1);
        g_csr[pos] = make_float2(g_dinv[s] * g_dinv[d], __int_as_float(s));
    }
}

// convert weights to f16 (W1 padded to 80 rows; fc1/fc2 too)
__global__ void k_wconv(const float* __restrict__ W1,
                        const float* __restrict__ W2,
                        const float* __restrict__ fc1_w,
                        const float* __restrict__ fc2_w) {
    int t = blockIdx.x * blockDim.x + threadIdx.x;
    if (t < 80 * 128) {
        int k = t >> 7;
        g_w1h[t] = __float2half((k < 78) ? W1[t] : 0.f);
    }
    if (t < 128 * 256) {
        g_w2h[t] = __float2half(W2[t]);
    }
    if (t < 320 * 512) {
        g_fc1h[t] = __float2half(fc1_w[t]);
    }
    if (t < 512) {
        g_fc2h[t] = __float2half(fc2_w[t]);
    }
}

// ---------------- GEMM1 (tensor cores): h1=relu(agg1@W1+b1) (fp8) -----------
__global__ __launch_bounds__(256) void k_gemm1(const float* __restrict__ b1) {
    __shared__ union {
        struct {
            uint4 a[128 * 11];   // f16 [128][88]
            uint4 b[80 * 17];    // f16 [80][136]
        } ld;
        float stg[128 * 68];
    } sm;
    int tid = threadIdx.x;
    int r0 = blockIdx.x * 128;
    int wid = tid >> 5;
    int wm = wid >> 1;      // 0..3
    int wn = wid & 1;       // 0..1

    const uint4 zero4 = make_uint4(0, 0, 0, 0);
    for (int idx = tid; idx < 128 * 10; idx += 256) {
        int r = idx / 10, u = idx - r * 10;
        int row = r0 + r;
        sm.ld.a[r * 11 + u] = (row < NN) ? g_agg1v[(long)row * 10 + u] : zero4;
    }
    const uint4* w1v = (const uint4*)g_w1h;
    for (int idx = tid; idx < 80 * 16; idx += 256) {
        int k = idx >> 4, u = idx & 15;
        sm.ld.b[k * 17 + u] = w1v[k * 16 + u];
    }
    __syncthreads();

    wmma::fragment<wmma::accumulator, 16, 16, 16, float> cf[2][4];
#pragma unroll
    for (int i = 0; i < 2; i++)
#pragma unroll
        for (int j = 0; j < 4; j++) wmma::fill_fragment(cf[i][j], 0.f);

    const __half* As = (const __half*)sm.ld.a;
    const __half* Bs = (const __half*)sm.ld.b;
#pragma unroll
    for (int k = 0; k < 80; k += 16) {
        wmma::fragment<wmma::matrix_a, 16, 16, 16, __half, wmma::row_major> af[2];
        wmma::load_matrix_sync(af[0], As + (wm * 32) * 88 + k, 88);
        wmma::load_matrix_sync(af[1], As + (wm * 32 + 16) * 88 + k, 88);
        wmma::fragment<wmma::matrix_b, 16, 16, 16, __half, wmma::row_major> bf[4];
#pragma unroll
        for (int j = 0; j < 4; j++)
            wmma::load_matrix_sync(bf[j], Bs + k * 136 + wn * 64 + j * 16, 136);
#pragma unroll
        for (int i = 0; i < 2; i++)
#pragma unroll
            for (int j = 0; j < 4; j++)
                wmma::mma_sync(cf[i][j], af[i], bf[j], cf[i][j]);
    }
    __syncthreads();

    unsigned short* h1q = (unsigned short*)g_h1qv;
#pragma unroll 1
    for (int ph = 0; ph < 2; ph++) {
        if (wn == ph) {
#pragma unroll
            for (int i = 0; i < 2; i++)
#pragma unroll
                for (int j = 0; j < 4; j++)
                    wmma::store_matrix_sync(
                        sm.stg + (wm * 32 + i * 16) * 68 + j * 16,
                        cf[i][j], 68, wmma::mem_row_major);
        }
        __syncthreads();
        for (int idx = tid; idx < 128 * 32; idx += 256) {
            int r = idx >> 5;
            int cp = idx & 31;
            int row = r0 + r;
            if (row < NN) {
                int col = ph * 64 + cp * 2;          // global column
                float v0 = sm.stg[r * 68 + cp * 2];  // local read
                float v1 = sm.stg[r * 68 + cp * 2 + 1];
                v0 = fmaxf(v0 + b1[col], 0.f);
                v1 = fmaxf(v1 + b1[col + 1], 0.f);
                __nv_fp8x2_e4m3 q2(make_float2(v0, v1));
                h1q[(long)row * 64 + (col >> 1)] = (unsigned short)q2.__x;
            }
        }
        __syncthreads();
    }
}

// ---------------- gather, layer 2 (CSR, no atomics, f32 accum) --------------
// half-warp per node; 16 lanes x uint2 cover the 128-fp8 h1 row.
__global__ __launch_bounds__(256) void k_gather2() {
    int hw = (blockIdx.x * blockDim.x + threadIdx.x) >> 4;   // half-warp id
    int q = threadIdx.x & 15;
    if (hw >= NN) return;
    int n = hw;

    float acc[8];
    // self-loop: h1[n] * (1/deg)
    {
        float inv = __ldg(g_inv + n);
        float f[8];
        fp8x8_to_f32x8(g_h1qv[(long)n * 16 + q], f);
#pragma unroll
        for (int j = 0; j < 8; j++) acc[j] = f[j] * inv;
    }

    int beg = __ldg(g_rowstart + n);
    int end = __ldg(g_rowstart + n + 1);
    if (beg < end) {
        float2 m = __ldg(g_csr + beg);
        for (int e = beg; e < end; e++) {
            float2 nxt = (e + 1 < end) ? __ldg(g_csr + e + 1) : m;
            int s = __float_as_int(m.y);
            float nrm = m.x;
            float f[8];
            fp8x8_to_f32x8(g_h1qv[(long)s * 16 + q], f);
#pragma unroll
            for (int j = 0; j < 8; j++) acc[j] += f[j] * nrm;
            m = nxt;
        }
    }

    uint4 outv;
    __half2* op = (__half2*)&outv;
#pragma unroll
    for (int j = 0; j < 4; j++)
        op[j] = __floats2half2_rn(acc[2 * j], acc[2 * j + 1]);
    g_agg2v[(long)n * 16 + q] = outv;
}

// ---------------- GEMM2 (tensor cores) + fused mean-pool epilogue -----------
__global__ __launch_bounds__(256) void k_gemm2(const float* __restrict__ b2,
                                               const int* __restrict__ batch) {
    __shared__ union {
        struct {
            uint4 a[128 * 9];    // f16 [128][72] (K chunk 64)
            uint4 b[64 * 17];    // f16 [64][136]
        } ld;
        float stg[128 * 68];
    } sm;
    int tid = threadIdx.x;
    int r0 = blockIdx.x * 128;
    int cb = blockIdx.y * 128;
    int wid = tid >> 5;
    int wm = wid >> 1;
    int wn = wid & 1;

    wmma::fragment<wmma::accumulator, 16, 16, 16, float> cf[2][4];
#pragma unroll
    for (int i = 0; i < 2; i++)
#pragma unroll
        for (int j = 0; j < 4; j++) wmma::fill_fragment(cf[i][j], 0.f);

    const uint4 zero4 = make_uint4(0, 0, 0, 0);
    const uint4* w2v = (const uint4*)g_w2h;   // rows of 32 uint4 (256 halves)
    const __half* As = (const __half*)sm.ld.a;
    const __half* Bs = (const __half*)sm.ld.b;

#pragma unroll 1
    for (int kc = 0; kc < 128; kc += 64) {
        __syncthreads();
        for (int idx = tid; idx < 128 * 8; idx += 256) {
            int r = idx >> 3, u = idx & 7;
            int row = r0 + r;
            sm.ld.a[r * 9 + u] =
                (row < NN) ? g_agg2v[(long)row * 16 + (kc >> 3) + u] : zero4;
        }
        for (int idx = tid; idx < 64 * 16; idx += 256) {
            int k = idx >> 4, u = idx & 15;
            sm.ld.b[k * 17 + u] = w2v[(kc + k) * 32 + (cb >> 3) + u];
        }
        __syncthreads();
#pragma unroll
        for (int k = 0; k < 64; k += 16) {
            wmma::fragment<wmma::matrix_a, 16, 16, 16, __half, wmma::row_major> af[2];
            wmma::load_matrix_sync(af[0], As + (wm * 32) * 72 + k, 72);
            wmma::load_matrix_sync(af[1], As + (wm * 32 + 16) * 72 + k, 72);
            wmma::fragment<wmma::matrix_b, 16, 16, 16, __half, wmma::row_major> bf[4];
#pragma unroll
            for (int j = 0; j < 4; j++)
                wmma::load_matrix_sync(bf[j], Bs + k * 136 + wn * 64 + j * 16, 136);
#pragma unroll
            for (int i = 0; i < 2; i++)
#pragma unroll
                for (int j = 0; j < 4; j++)
                    wmma::mma_sync(cf[i][j], af[i], bf[j], cf[i][j]);
        }
    }
    __syncthreads();

#pragma unroll 1
    for (int ph = 0; ph < 2; ph++) {
        if (wn == ph) {
#pragma unroll
            for (int i = 0; i < 2; i++)
#pragma unroll
                for (int j = 0; j < 4; j++)
                    wmma::store_matrix_sync(
                        sm.stg + (wm * 32 + i * 16) * 68 + j * 16,
                        cf[i][j], 68, wmma::mem_row_major);
        }
        __syncthreads();
        for (int idx = tid; idx < 128 * 16; idx += 256) {
            int r = idx >> 4;
            int qd = idx & 15;
            int row = r0 + r;
            if (row < NN) {
                int lcol = qd * 4;                   // local staged column
                int gcol = cb + ph * 64 + lcol;      // global output column
                float v0 = fmaxf(sm.stg[r * 68 + lcol + 0] + b2[gcol + 0], 0.f);
                float v1 = fmaxf(sm.stg[r * 68 + lcol + 1] + b2[gcol + 1], 0.f);
                float v2 = fmaxf(sm.stg[r * 68 + lcol + 2] + b2[gcol + 2], 0.f);
                float v3 = fmaxf(sm.stg[r * 68 + lcol + 3] + b2[gcol + 3], 0.f);
                int g = __ldg(batch + row);
                float* p = g_sums + g * 256 + gcol;
                asm volatile("red.global.add.v4.f32 [%0], {%1,%2,%3,%4};"
                             :: "l"(p), "f"(v0), "f"(v1), "f"(v2), "f"(v3)
                             : "memory");
            }
        }
        __syncthreads();
    }
}

// ---------------- protein path -----------------------------------------------
__global__ void k_ptable(const float* __restrict__ emb,
                         const float* __restrict__ conv_w) {
    int idx = blockIdx.x * blockDim.x + threadIdx.x;
    if (idx < 25 * 8 * 64) {
        int o = idx & 63;
        int k = (idx >> 6) & 7;
        int tok = idx >> 9;
        float s = 0.f;
#pragma unroll 4
        for (int i = 0; i < 128; i++)
            s += emb[tok * 128 + i] * conv_w[o * 1024 + i * 8 + k];
        g_ptab[tok * 512 + k * 64 + o] = s;
    }
}

__global__ __launch_bounds__(256) void k_conv(const int* __restrict__ seq,
                                              const float* __restrict__ conv_b) {
    __shared__ float2 stab[25 * 8 * 16];   // [tok][k][chan-pair]
    __shared__ int sseq[1024];
    __shared__ float2 sred[256];
    int tid = threadIdx.x;
    int b = blockIdx.x;
    int co = blockIdx.y * 32;

    for (int idx = tid; idx < 1024; idx += 256) sseq[idx] = seq[b * 1024 + idx];
    for (int idx = tid; idx < 25 * 8 * 16; idx += 256) {
        int p = idx & 15;
        int kk = (idx >> 4) & 7;
        int tok = idx >> 7;
        stab[idx] = make_float2(g_ptab[tok * 512 + kk * 64 + co + 2 * p],
                                g_ptab[tok * 512 + kk * 64 + co + 2 * p + 1]);
    }
    __syncthreads();

    int p = tid & 15;
    int phase = tid >> 4;
    float2 m = make_float2(-1e30f, -1e30f);
    for (int l = phase; l < 1017; l += 16) {
        float sx = 0.f, sy = 0.f;
#pragma unroll
        for (int k = 0; k < 8; k++) {
            float2 v = stab[(sseq[l + k] * 8 + k) * 16 + p];
            sx += v.x; sy += v.y;
        }
        m.x = fmaxf(m.x, sx);
        m.y = fmaxf(m.y, sy);
    }
    sred[tid] = m;
    __syncthreads();
    if (tid < 16) {
        float2 mm = sred[tid];
#pragma unroll
        for (int g = 1; g < 16; g++) {
            float2 v = sred[g * 16 + tid];
            mm.x = fmaxf(mm.x, v.x);
            mm.y = fmaxf(mm.y, v.y);
        }
        g_prot[b * 64 + co + 2 * tid]     = fmaxf(mm.x + conv_b[co + 2 * tid], 0.f);
        g_prot[b * 64 + co + 2 * tid + 1] = fmaxf(mm.y + conv_b[co + 2 * tid + 1], 0.f);
    }
}

// ---------------- final MLP (f16 weights) -------------------------------------
__global__ __launch_bounds__(256) void k_final(const float* __restrict__ fc1_b,
                                               const float* __restrict__ fc2_b,
                                               float* __restrict__ out) {
    __shared__ float comb[320];
    __shared__ float sred[256];
    int tid = threadIdx.x;
    int b = blockIdx.x;
    float invc = 1.0f / fmaxf(g_cnt[b], 1.0f);
    if (tid < 256) comb[tid] = g_sums[b * 256 + tid] * invc;
    if (tid < 64) comb[256 + tid] = g_prot[b * 64 + tid];
    __syncthreads();

    float part = 0.f;
#pragma unroll
    for (int rep = 0; rep < 2; rep++) {
        int o = tid + rep * 256;
        float acc = fc1_b[o];
#pragma unroll 4
        for (int j = 0; j < 320; j++)
            acc += comb[j] * __half2float(g_fc1h[j * 512 + o]);
        part += fmaxf(acc, 0.f) * __half2float(g_fc2h[o]);
    }
    sred[tid] = part;
    __syncthreads();
    for (int s = 128; s > 0; s >>= 1) {
        if (tid < s) sred[tid] += sred[tid + s];
        __syncthreads();
    }
    if (tid == 0) out[b] = sred[0] + fc2_b[0];
}

// ---------------- launch ------------------------------------------------------
extern "C" void kernel_launch(void* const* d_in, const int* in_sizes, int n_in,
                              void* d_out, int out_size) {
    const float* x       = (const float*)d_in[0];
    const int*   ei      = (const int*)  d_in[1];   // [2, NE]
    const int*   batch   = (const int*)  d_in[2];
    const int*   seq     = (const int*)  d_in[3];   // [NG, 1024]
    const float* W1      = (const float*)d_in[4];
    const float* b1      = (const float*)d_in[5];
    const float* W2      = (const float*)d_in[6];
    const float* b2      = (const float*)d_in[7];
    const float* emb     = (const float*)d_in[8];
    const float* conv_w  = (const float*)d_in[9];
    const float* conv_b  = (const float*)d_in[10];
    const float* fc1_w   = (const float*)d_in[11];
    const float* fc1_b   = (const float*)d_in[12];
    const float* fc2_w   = (const float*)d_in[13];
    const float* fc2_b   = (const float*)d_in[14];
    float* out = (float*)d_out;

    const int* src = ei;
    const int* dst = ei + NE;

    k_zero<<<512, 256>>>();                                   // 1
    k_deg<<<(NE + 255) / 256, 256>>>(dst);                    // 2
    k_init1<<<(NN * 10 + 255) / 256, 256>>>(x, batch);        // 3
    k_scatter1<<<2048, 256>>>(src, dst);                      // 4  <- profiled
    k_scan<<<1, 1024>>>();                                    // 5
    k_fill<<<(NE + 255) / 256, 256>>>(src, dst);              // 6
    k_wconv<<<(320 * 512 + 255) / 256, 256>>>(W1, W2, fc1_w, fc2_w); // 7
    k_gemm1<<<(NN + 127) / 128, 256>>>(b1);                   // 8
    k_gather2<<<(NN * 16 + 255) / 256, 256>>>();              // 9
    {
        dim3 grid((NN + 127) / 128, 2);
        k_gemm2<<<grid, 256>>>(b2, batch);                    // 10
    }
    k_ptable<<<(25 * 8 * 64 + 255) / 256, 256>>>(emb, conv_w);// 11
    {
        dim3 grid(NG, 2);
        k_conv<<<grid, 256>>>(seq, conv_b);                   // 12
    }
    k_final<<<NG, 256>>>(fc1_b, fc2_b, out);                  // 13
}

// round 13
// speedup vs baseline: 1.3728x; 1.3728x over previous
#include <cuda_runtime.h>
#include <cuda_fp16.h>
#include <cuda_fp8.h>
#include <mma.h>

using namespace nvcuda;

#define NN 100000
#define NE 1600000
#define NG 512

// ---------------- scratch (device globals; no allocations allowed) ----------
__device__ int    g_cnti[NN];         // int in-degree counts (deg = cnti + 1)
__device__ float  g_dinv[NN];         // rsqrt(deg)
__device__ float  g_inv[NN];          // 1/deg
__device__ uint4  g_x16v[NN * 10];    // x as __half[NN*80] (cols 78,79 = 0)
__device__ uint4  g_agg1v[NN * 10];   // aggregated x as __half[NN*80]
__device__ uint2  g_h1qv[NN * 16];    // relu(gcn1) as fp8 e4m3 [NN*128]
__device__ uint4  g_agg2v[NN * 16];   // aggregated h1 as __half[NN*128]
__device__ __half g_w1h[80 * 128];    // W1 as f16, K padded to 80
__device__ __half g_w2h[128 * 256];   // W2 as f16
__device__ __half g_fc1h[320 * 512];  // fc1_w as f16
__device__ __half g_fc2h[512];        // fc2_w as f16
__device__ uint4  g_comb4[512 * 40];  // comb [NG,320] as f16 (uint4-aligned)
__device__ float  g_sums[NG * 256];   // per-graph sums of h2
__device__ float  g_cnt[NG];          // per-graph node counts
__device__ float  g_ptab[25 * 8 * 64];// precomputed emb@conv_w table [tok][k][o]
__device__ float  g_prot[NG * 64];    // protein features after maxpool

// f16x8 reduction helper: p += v * nh (elementwise, 8 halves)
__device__ __forceinline__ void red_f16x8(__half* p, uint4 v, __half2 nh) {
    __half2 h0 = __hmul2(*(const __half2*)&v.x, nh);
    __half2 h1 = __hmul2(*(const __half2*)&v.y, nh);
    __half2 h2 = __hmul2(*(const __half2*)&v.z, nh);
    __half2 h3 = __hmul2(*(const __half2*)&v.w, nh);
    asm volatile("red.global.add.noftz.v4.f16x2 [%0], {%1,%2,%3,%4};"
                 :: "l"(p),
                    "r"(*(const unsigned int*)&h0), "r"(*(const unsigned int*)&h1),
                    "r"(*(const unsigned int*)&h2), "r"(*(const unsigned int*)&h3)
                 : "memory");
}

// 8 fp8(e4m3) packed in uint2 -> 8 f16 packed in uint4
__device__ __forceinline__ uint4 fp8x8_to_f16x8(uint2 qv) {
    uint4 r;
    __half2_raw a0 = __nv_cvt_fp8x2_to_halfraw2(
        (__nv_fp8x2_storage_t)(qv.x & 0xFFFF), __NV_E4M3);
    __half2_raw a1 = __nv_cvt_fp8x2_to_halfraw2(
        (__nv_fp8x2_storage_t)(qv.x >> 16), __NV_E4M3);
    __half2_raw a2 = __nv_cvt_fp8x2_to_halfraw2(
        (__nv_fp8x2_storage_t)(qv.y & 0xFFFF), __NV_E4M3);
    __half2_raw a3 = __nv_cvt_fp8x2_to_halfraw2(
        (__nv_fp8x2_storage_t)(qv.y >> 16), __NV_E4M3);
    r.x = *(unsigned int*)&a0;
    r.y = *(unsigned int*)&a1;
    r.z = *(unsigned int*)&a2;
    r.w = *(unsigned int*)&a3;
    return r;
}

// ---------------- zero + degree count ----------------------------------------
__global__ void k_zero(float* __restrict__ out, const float* __restrict__ fc2_b) {
    int t = blockIdx.x * blockDim.x + threadIdx.x;
    int stride = gridDim.x * blockDim.x;
    for (int i = t; i < NN; i += stride) g_cnti[i] = 0;
    for (int i = t; i < NG * 256; i += stride) g_sums[i] = 0.f;
    for (int i = t; i < NG; i += stride) { g_cnt[i] = 0.f; out[i] = fc2_b[0]; }
}

__global__ void k_deg(const int* __restrict__ dst) {
    int t = blockIdx.x * blockDim.x + threadIdx.x;
    if (t < NE) atomicAdd(&g_cnti[dst[t]], 1);
}

// init: x16 = f16(x) zero-padded to 80; agg1 = f16(x/deg); dinv/inv per node;
// also the per-graph node count.
__global__ void k_init1(const float* __restrict__ x,
                        const int* __restrict__ batch) {
    int t = blockIdx.x * blockDim.x + threadIdx.x;
    if (t < NN * 10) {
        int i = t / 10;
        int q = t - i * 10;
        float d = (float)g_cnti[i] + 1.0f;
        float inv = 1.0f / d;
        if (q == 0) {
            g_dinv[i] = rsqrtf(d);
            g_inv[i] = inv;
            atomicAdd(&g_cnt[batch[i]], 1.0f);
        }
        float v[8];
        if (q < 9) {
            const float2* xp = (const float2*)(x + (long)i * 78 + q * 8);
#pragma unroll
            for (int j = 0; j < 4; j++) {
                float2 a = xp[j];
                v[2 * j] = a.x; v[2 * j + 1] = a.y;
            }
        } else {
            const float2* xp = (const float2*)(x + (long)i * 78 + 72);
#pragma unroll
            for (int j = 0; j < 3; j++) {
                float2 a = xp[j];
                v[2 * j] = a.x; v[2 * j + 1] = a.y;
            }
            v[6] = 0.f; v[7] = 0.f;
        }
        uint4 raw, agg;
        __half2* rp = (__half2*)&raw;
        __half2* ap = (__half2*)&agg;
#pragma unroll
        for (int j = 0; j < 4; j++) {
            rp[j] = __floats2half2_rn(v[2 * j], v[2 * j + 1]);
            ap[j] = __floats2half2_rn(v[2 * j] * inv, v[2 * j + 1] * inv);
        }
        g_x16v[(long)i * 10 + q] = raw;
        g_agg1v[(long)i * 10 + q] = agg;
    }
}

// ---------------- edge scatter, layer 1 (f16, flat chunk space) -------------
__global__ void k_scatter1(const int* __restrict__ src,
                           const int* __restrict__ dst) {
    const int W = 2048 * 8;                 // total warps
    const int EPW = (NE + W - 1) / W;       // 98 edges per warp
    int w = (blockIdx.x * blockDim.x + threadIdx.x) >> 5;
    int lane = threadIdx.x & 31;
    int e0 = w * EPW;
    if (e0 >= NE) return;
    int ecnt = min(EPW, NE - e0);
    int nchunk = ecnt * 10;
    __half* agg = (__half*)g_agg1v;

    int c = lane;
    for (; c + 32 < nchunk; c += 64) {
        int c0 = c, c1 = c + 32;
        int le0 = c0 / 10, q0 = c0 - le0 * 10;
        int le1 = c1 / 10, q1 = c1 - le1 * 10;
        int e0i = e0 + le0, e1i = e0 + le1;
        int s0 = __ldg(src + e0i), d0 = __ldg(dst + e0i);
        int s1 = __ldg(src + e1i), d1 = __ldg(dst + e1i);
        float n0 = __ldg(g_dinv + s0) * __ldg(g_dinv + d0);
        float n1 = __ldg(g_dinv + s1) * __ldg(g_dinv + d1);
        uint4 v0 = g_x16v[(long)s0 * 10 + q0];
        uint4 v1 = g_x16v[(long)s1 * 10 + q1];
        red_f16x8(agg + (long)d0 * 80 + q0 * 8, v0, __float2half2_rn(n0));
        red_f16x8(agg + (long)d1 * 80 + q1 * 8, v1, __float2half2_rn(n1));
    }
    for (; c < nchunk; c += 32) {
        int le = c / 10, q = c - le * 10;
        int e = e0 + le;
        int s = __ldg(src + e), d = __ldg(dst + e);
        float nrm = __ldg(g_dinv + s) * __ldg(g_dinv + d);
        uint4 v = g_x16v[(long)s * 10 + q];
        red_f16x8(agg + (long)d * 80 + q * 8, v, __float2half2_rn(nrm));
    }
}

// ---------------- prep: weights to f16 + emb@conv_w table (merged) ----------
__global__ void k_prep(const float* __restrict__ W1,
                       const float* __restrict__ W2,
                       const float* __restrict__ fc1_w,
                       const float* __restrict__ fc2_w,
                       const float* __restrict__ emb,
                       const float* __restrict__ conv_w) {
    int t = blockIdx.x * blockDim.x + threadIdx.x;
    if (t < 80 * 128) {
        int k = t >> 7;
        g_w1h[t] = __float2half((k < 78) ? W1[t] : 0.f);
    }
    if (t < 128 * 256) {
        g_w2h[t] = __float2half(W2[t]);
    }
    if (t < 320 * 512) {
        g_fc1h[t] = __float2half(fc1_w[t]);
    }
    if (t < 512) {
        g_fc2h[t] = __float2half(fc2_w[t]);
    }
    if (t < 25 * 8 * 64) {
        int o = t & 63;
        int k = (t >> 6) & 7;
        int tok = t >> 9;
        float s = 0.f;
#pragma unroll 4
        for (int i = 0; i < 128; i++)
            s += emb[tok * 128 + i] * conv_w[o * 1024 + i * 8 + k];
        g_ptab[tok * 512 + k * 64 + o] = s;
    }
}

// ---------------- GEMM1 (tensor cores): h1=relu(agg1@W1+b1) (fp8); agg2=h1/deg
__global__ __launch_bounds__(256) void k_gemm1(const float* __restrict__ b1) {
    __shared__ union {
        struct {
            uint4 a[128 * 11];   // f16 [128][88]
            uint4 b[80 * 17];    // f16 [80][136]
        } ld;
        float stg[128 * 68];
    } sm;
    int tid = threadIdx.x;
    int r0 = blockIdx.x * 128;
    int wid = tid >> 5;
    int wm = wid >> 1;      // 0..3
    int wn = wid & 1;       // 0..1

    const uint4 zero4 = make_uint4(0, 0, 0, 0);
    for (int idx = tid; idx < 128 * 10; idx += 256) {
        int r = idx / 10, u = idx - r * 10;
        int row = r0 + r;
        sm.ld.a[r * 11 + u] = (row < NN) ? g_agg1v[(long)row * 10 + u] : zero4;
    }
    const uint4* w1v = (const uint4*)g_w1h;
    for (int idx = tid; idx < 80 * 16; idx += 256) {
        int k = idx >> 4, u = idx & 15;
        sm.ld.b[k * 17 + u] = w1v[k * 16 + u];
    }
    __syncthreads();

    wmma::fragment<wmma::accumulator, 16, 16, 16, float> cf[2][4];
#pragma unroll
    for (int i = 0; i < 2; i++)
#pragma unroll
        for (int j = 0; j < 4; j++) wmma::fill_fragment(cf[i][j], 0.f);

    const __half* As = (const __half*)sm.ld.a;
    const __half* Bs = (const __half*)sm.ld.b;
#pragma unroll
    for (int k = 0; k < 80; k += 16) {
        wmma::fragment<wmma::matrix_a, 16, 16, 16, __half, wmma::row_major> af[2];
        wmma::load_matrix_sync(af[0], As + (wm * 32) * 88 + k, 88);
        wmma::load_matrix_sync(af[1], As + (wm * 32 + 16) * 88 + k, 88);
        wmma::fragment<wmma::matrix_b, 16, 16, 16, __half, wmma::row_major> bf[4];
#pragma unroll
        for (int j = 0; j < 4; j++)
            wmma::load_matrix_sync(bf[j], Bs + k * 136 + wn * 64 + j * 16, 136);
#pragma unroll
        for (int i = 0; i < 2; i++)
#pragma unroll
            for (int j = 0; j < 4; j++)
                wmma::mma_sync(cf[i][j], af[i], bf[j], cf[i][j]);
    }
    __syncthreads();

    unsigned short* h1q = (unsigned short*)g_h1qv;
    __half* a2 = (__half*)g_agg2v;
#pragma unroll 1
    for (int ph = 0; ph < 2; ph++) {
        if (wn == ph) {
#pragma unroll
            for (int i = 0; i < 2; i++)
#pragma unroll
                for (int j = 0; j < 4; j++)
                    wmma::store_matrix_sync(
                        sm.stg + (wm * 32 + i * 16) * 68 + j * 16,
                        cf[i][j], 68, wmma::mem_row_major);
        }
        __syncthreads();
        for (int idx = tid; idx < 128 * 32; idx += 256) {
            int r = idx >> 5;
            int cp = idx & 31;
            int row = r0 + r;
            if (row < NN) {
                int col = ph * 64 + cp * 2;          // global column
                float v0 = sm.stg[r * 68 + cp * 2];  // local read
                float v1 = sm.stg[r * 68 + cp * 2 + 1];
                v0 = fmaxf(v0 + b1[col], 0.f);
                v1 = fmaxf(v1 + b1[col + 1], 0.f);
                float inv = __ldg(g_inv + row);
                __nv_fp8x2_e4m3 q2(make_float2(v0, v1));
                h1q[(long)row * 64 + (col >> 1)] = (unsigned short)q2.__x;
                *(__half2*)(a2 + (long)row * 128 + col) =
                    __floats2half2_rn(v0 * inv, v1 * inv);
            }
        }
        __syncthreads();
    }
}

// ---------------- edge scatter, layer 2 (fp8 read, f16 RED) -----------------
__global__ void k_scatter2(const int* __restrict__ src,
                           const int* __restrict__ dst) {
    const int W = 2048 * 8;
    const int EPW = (NE + W - 1) / W;       // 98
    int w = (blockIdx.x * blockDim.x + threadIdx.x) >> 5;
    int lane = threadIdx.x & 31;
    int half = lane >> 4;
    int q = lane & 15;
    int e = w * EPW;
    int end = min(e + EPW, NE);
    if (e >= NE) return;
    __half* agg = (__half*)g_agg2v;

    for (; e + 3 < end; e += 4) {
        int ea = e + half, eb = e + 2 + half;
        int sa = __ldg(src + ea), da = __ldg(dst + ea);
        int sb = __ldg(src + eb), db = __ldg(dst + eb);
        float na = __ldg(g_dinv + sa) * __ldg(g_dinv + da);
        float nb = __ldg(g_dinv + sb) * __ldg(g_dinv + db);
        uint2 qa = g_h1qv[(long)sa * 16 + q];
        uint2 qb = g_h1qv[(long)sb * 16 + q];
        uint4 va = fp8x8_to_f16x8(qa);
        uint4 vb = fp8x8_to_f16x8(qb);
        red_f16x8(agg + (long)da * 128 + q * 8, va, __float2half2_rn(na));
        red_f16x8(agg + (long)db * 128 + q * 8, vb, __float2half2_rn(nb));
    }
    for (; e < end; e += 2) {
        if (e + half < end) {
            int ei = e + half;
            int s = __ldg(src + ei), d = __ldg(dst + ei);
            float nrm = __ldg(g_dinv + s) * __ldg(g_dinv + d);
            uint2 qv = g_h1qv[(long)s * 16 + q];
            uint4 v = fp8x8_to_f16x8(qv);
            red_f16x8(agg + (long)d * 128 + q * 8, v, __float2half2_rn(nrm));
        }
    }
}

// ---------------- GEMM2 (tensor cores) + fused mean-pool epilogue -----------
__global__ __launch_bounds__(256) void k_gemm2(const float* __restrict__ b2,
                                               const int* __restrict__ batch) {
    __shared__ union {
        struct {
            uint4 a[128 * 9];    // f16 [128][72] (K chunk 64)
            uint4 b[64 * 17];    // f16 [64][136]
        } ld;
        float stg[128 * 68];
    } sm;
    int tid = threadIdx.x;
    int r0 = blockIdx.x * 128;
    int cb = blockIdx.y * 128;
    int wid = tid >> 5;
    int wm = wid >> 1;
    int wn = wid & 1;

    wmma::fragment<wmma::accumulator, 16, 16, 16, float> cf[2][4];
#pragma unroll
    for (int i = 0; i < 2; i++)
#pragma unroll
        for (int j = 0; j < 4; j++) wmma::fill_fragment(cf[i][j], 0.f);

    const uint4 zero4 = make_uint4(0, 0, 0, 0);
    const uint4* w2v = (const uint4*)g_w2h;   // rows of 32 uint4 (256 halves)
    const __half* As = (const __half*)sm.ld.a;
    const __half* Bs = (const __half*)sm.ld.b;

#pragma unroll 1
    for (int kc = 0; kc < 128; kc += 64) {
        __syncthreads();
        for (int idx = tid; idx < 128 * 8; idx += 256) {
            int r = idx >> 3, u = idx & 7;
            int row = r0 + r;
            sm.ld.a[r * 9 + u] =
                (row < NN) ? g_agg2v[(long)row * 16 + (kc >> 3) + u] : zero4;
        }
        for (int idx = tid; idx < 64 * 16; idx += 256) {
            int k = idx >> 4, u = idx & 15;
            sm.ld.b[k * 17 + u] = w2v[(kc + k) * 32 + (cb >> 3) + u];
        }
        __syncthreads();
#pragma unroll
        for (int k = 0; k < 64; k += 16) {
            wmma::fragment<wmma::matrix_a, 16, 16, 16, __half, wmma::row_major> af[2];
            wmma::load_matrix_sync(af[0], As + (wm * 32) * 72 + k, 72);
            wmma::load_matrix_sync(af[1], As + (wm * 32 + 16) * 72 + k, 72);
            wmma::fragment<wmma::matrix_b, 16, 16, 16, __half, wmma::row_major> bf[4];
#pragma unroll
            for (int j = 0; j < 4; j++)
                wmma::load_matrix_sync(bf[j], Bs + k * 136 + wn * 64 + j * 16, 136);
#pragma unroll
            for (int i = 0; i < 2; i++)
#pragma unroll
                for (int j = 0; j < 4; j++)
                    wmma::mma_sync(cf[i][j], af[i], bf[j], cf[i][j]);
        }
    }
    __syncthreads();

#pragma unroll 1
    for (int ph = 0; ph < 2; ph++) {
        if (wn == ph) {
#pragma unroll
            for (int i = 0; i < 2; i++)
#pragma unroll
                for (int j = 0; j < 4; j++)
                    wmma::store_matrix_sync(
                        sm.stg + (wm * 32 + i * 16) * 68 + j * 16,
                        cf[i][j], 68, wmma::mem_row_major);
        }
        __syncthreads();
        for (int idx = tid; idx < 128 * 16; idx += 256) {
            int r = idx >> 4;
            int qd = idx & 15;
            int row = r0 + r;
            if (row < NN) {
                int lcol = qd * 4;                   // local staged column
                int gcol = cb + ph * 64 + lcol;      // global output column
                float v0 = fmaxf(sm.stg[r * 68 + lcol + 0] + b2[gcol + 0], 0.f);
                float v1 = fmaxf(sm.stg[r * 68 + lcol + 1] + b2[gcol + 1], 0.f);
                float v2 = fmaxf(sm.stg[r * 68 + lcol + 2] + b2[gcol + 2], 0.f);
                float v3 = fmaxf(sm.stg[r * 68 + lcol + 3] + b2[gcol + 3], 0.f);
                int g = __ldg(batch + row);
                float* p = g_sums + g * 256 + gcol;
                asm volatile("red.global.add.v4.f32 [%0], {%1,%2,%3,%4};"
                             :: "l"(p), "f"(v0), "f"(v1), "f"(v2), "f"(v3)
                             : "memory");
            }
        }
        __syncthreads();
    }
}

// ---------------- protein conv ------------------------------------------------
__global__ __launch_bounds__(256) void k_conv(const int* __restrict__ seq,
                                              const float* __restrict__ conv_b) {
    __shared__ float2 stab[25 * 8 * 16];   // [tok][k][chan-pair]
    __shared__ int sseq[1024];
    __shared__ float2 sred[256];
    int tid = threadIdx.x;
    int b = blockIdx.x;
    int co = blockIdx.y * 32;

    for (int idx = tid; idx < 1024; idx += 256) sseq[idx] = seq[b * 1024 + idx];
    for (int idx = tid; idx < 25 * 8 * 16; idx += 256) {
        int p = idx & 15;
        int kk = (idx >> 4) & 7;
        int tok = idx >> 7;
        stab[idx] = make_float2(g_ptab[tok * 512 + kk * 64 + co + 2 * p],
                                g_ptab[tok * 512 + kk * 64 + co + 2 * p + 1]);
    }
    __syncthreads();

    int p = tid & 15;
    int phase = tid >> 4;
    float2 m = make_float2(-1e30f, -1e30f);
    for (int l = phase; l < 1017; l += 16) {
        float sx = 0.f, sy = 0.f;
#pragma unroll
        for (int k = 0; k < 8; k++) {
            float2 v = stab[(sseq[l + k] * 8 + k) * 16 + p];
            sx += v.x; sy += v.y;
        }
        m.x = fmaxf(m.x, sx);
        m.y = fmaxf(m.y, sy);
    }
    sred[tid] = m;
    __syncthreads();
    if (tid < 16) {
        float2 mm = sred[tid];
#pragma unroll
        for (int g = 1; g < 16; g++) {
            float2 v = sred[g * 16 + tid];
            mm.x = fmaxf(mm.x, v.x);
            mm.y = fmaxf(mm.y, v.y);
        }
        g_prot[b * 64 + co + 2 * tid]     = fmaxf(mm.x + conv_b[co + 2 * tid], 0.f);
        g_prot[b * 64 + co + 2 * tid + 1] = fmaxf(mm.y + conv_b[co + 2 * tid + 1], 0.f);
    }
}

// ---------------- build comb [NG,320] f16 -------------------------------------
__global__ void k_comb() {
    int t = blockIdx.x * blockDim.x + threadIdx.x;
    if (t < NG * 320) {
        int g = t / 320;
        int j = t - g * 320;
        float invc = 1.0f / fmaxf(g_cnt[g], 1.0f);
        float v = (j < 256) ? g_sums[g * 256 + j] * invc
                            : g_prot[g * 64 + (j - 256)];
        ((__half*)g_comb4)[t] = __float2half(v);
    }
}

// ---------------- final MLP as tensor-core GEMM ------------------------------
// M=512(graphs), N=512(fc1 out), K=320. grid (4,4); epilogue: relu(+b)·fc2 -> out
__global__ __launch_bounds__(256) void k_gemmf(const float* __restrict__ fc1_b,
                                               float* __restrict__ out) {
    __shared__ union {
        struct {
            uint4 a[128 * 9];    // f16 [128][72] (K chunk 64)
            uint4 b[64 * 17];    // f16 [64][136]
        } ld;
        float stg[128 * 68];
    } sm;
    __shared__ float rowsum[128];
    int tid = threadIdx.x;
    int r0 = blockIdx.x * 128;
    int cb = blockIdx.y * 128;
    int wid = tid >> 5;
    int wm = wid >> 1;
    int wn = wid & 1;

    wmma::fragment<wmma::accumulator, 16, 16, 16, float> cf[2][4];
#pragma unroll
    for (int i = 0; i < 2; i++)
#pragma unroll
        for (int j = 0; j < 4; j++) wmma::fill_fragment(cf[i][j], 0.f);

    const uint4* av = g_comb4;                // row stride 40 uint4 (320 halves)
    const uint4* bv = (const uint4*)g_fc1h;   // row stride 64 uint4 (512 halves)
    const __half* As = (const __half*)sm.ld.a;
    const __half* Bs = (const __half*)sm.ld.b;

#pragma unroll 1
    for (int kc = 0; kc < 320; kc += 64) {
        __syncthreads();
        for (int idx = tid; idx < 128 * 8; idx += 256) {
            int r = idx >> 3, u = idx & 7;
            sm.ld.a[r * 9 + u] = av[(r0 + r) * 40 + (kc >> 3) + u];
        }
        for (int idx = tid; idx < 64 * 16; idx += 256) {
            int k = idx >> 4, u = idx & 15;
            sm.ld.b[k * 17 + u] = bv[(kc + k) * 64 + (cb >> 3) + u];
        }
        __syncthreads();
#pragma unroll
        for (int k = 0; k < 64; k += 16) {
            wmma::fragment<wmma::matrix_a, 16, 16, 16, __half, wmma::row_major> af[2];
            wmma::load_matrix_sync(af[0], As + (wm * 32) * 72 + k, 72);
            wmma::load_matrix_sync(af[1], As + (wm * 32 + 16) * 72 + k, 72);
            wmma::fragment<wmma::matrix_b, 16, 16, 16, __half, wmma::row_major> bf[4];
#pragma unroll
            for (int j = 0; j < 4; j++)
                wmma::load_matrix_sync(bf[j], Bs + k * 136 + wn * 64 + j * 16, 136);
#pragma unroll
            for (int i = 0; i < 2; i++)
#pragma unroll
                for (int j = 0; j < 4; j++)
                    wmma::mma_sync(cf[i][j], af[i], bf[j], cf[i][j]);
        }
    }
    __syncthreads();
    if (tid < 128) rowsum[tid] = 0.f;
    __syncthreads();

#pragma unroll 1
    for (int ph = 0; ph < 2; ph++) {
        if (wn == ph) {
#pragma unroll
            for (int i = 0; i < 2; i++)
#pragma unroll
                for (int j = 0; j < 4; j++)
                    wmma::store_matrix_sync(
                        sm.stg + (wm * 32 + i * 16) * 68 + j * 16,
                        cf[i][j], 68, wmma::mem_row_major);
        }
        __syncthreads();
        for (int idx = tid; idx < 128 * 16; idx += 256) {
            int r = idx >> 4;
            int qd = idx & 15;
            int lcol = qd * 4;
            int gcol = cb + ph * 64 + lcol;
            float p = 0.f;
#pragma unroll
            for (int i = 0; i < 4; i++) {
                float v = fmaxf(sm.stg[r * 68 + lcol + i] + fc1_b[gcol + i], 0.f);
                p += v * __half2float(g_fc2h[gcol + i]);
            }
            atomicAdd(&rowsum[r], p);
        }
        __syncthreads();
    }
    if (tid < 128) atomicAdd(&out[r0 + tid], rowsum[tid]);
}

// ---------------- launch ------------------------------------------------------
extern "C" void kernel_launch(void* const* d_in, const int* in_sizes, int n_in,
                              void* d_out, int out_size) {
    const float* x       = (const float*)d_in[0];
    const int*   ei      = (const int*)  d_in[1];   // [2, NE]
    const int*   batch   = (const int*)  d_in[2];
    const int*   seq     = (const int*)  d_in[3];   // [NG, 1024]
    const float* W1      = (const float*)d_in[4];
    const float* b1      = (const float*)d_in[5];
    const float* W2      = (const float*)d_in[6];
    const float* b2      = (const float*)d_in[7];
    const float* emb     = (const float*)d_in[8];
    const float* conv_w  = (const float*)d_in[9];
    const float* conv_b  = (const float*)d_in[10];
    const float* fc1_w   = (const float*)d_in[11];
    const float* fc1_b   = (const float*)d_in[12];
    const float* fc2_w   = (const float*)d_in[13];
    const float* fc2_b   = (const float*)d_in[14];
    float* out = (float*)d_out;

    const int* src = ei;
    const int* dst = ei + NE;

    k_zero<<<512, 256>>>(out, fc2_b);                         // 1
    k_deg<<<(NE + 255) / 256, 256>>>(dst);                    // 2
    k_init1<<<(NN * 10 + 255) / 256, 256>>>(x, batch);        // 3
    k_scatter1<<<2048, 256>>>(src, dst);                      // 4  <- profiled
    k_prep<<<(320 * 512 + 255) / 256, 256>>>(W1, W2, fc1_w, fc2_w,
                                             emb, conv_w);    // 5
    k_gemm1<<<(NN + 127) / 128, 256>>>(b1);                   // 6
    k_scatter2<<<2048, 256>>>(src, dst);                      // 7
    {
        dim3 grid((NN + 127) / 128, 2);
        k_gemm2<<<grid, 256>>>(b2, batch);                    // 8
    }
    {
        dim3 grid(NG, 2);
        k_conv<<<grid, 256>>>(seq, conv_b);                   // 9
    }
    k_comb<<<(NG * 320 + 255) / 256, 256>>>();                // 10
    {
        dim3 grid(4, 4);
        k_gemmf<<<grid, 256>>>(fc1_b, out);                   // 11
    }
}

// round 14
// speedup vs baseline: 1.3841x; 1.0082x over previous
#include <cuda_runtime.h>
#include <cuda_fp16.h>
#include <cuda_fp8.h>
#include <mma.h>

using namespace nvcuda;

#define NN 100000
#define NE 1600000
#define NG 512

// ---------------- scratch (device globals; no allocations allowed) ----------
__device__ int    g_cnti[NN];         // int in-degree counts (deg = cnti + 1)
__device__ float  g_inv[NN];          // 1/deg
__device__ float4 g_emeta[NE];        // per-edge {src, dst, norm, pad}
__device__ uint4  g_x16v[NN * 10];    // x as __half[NN*80] (cols 78,79 = 0)
__device__ uint4  g_agg1v[NN * 10];   // aggregated x as __half[NN*80]
__device__ uint2  g_h1qv[NN * 16];    // relu(gcn1) as fp8 e4m3 [NN*128]
__device__ uint4  g_agg2v[NN * 16];   // aggregated h1 as __half[NN*128]
__device__ __half g_w1h[80 * 128];    // W1 as f16, K padded to 80
__device__ __half g_w2h[128 * 256];   // W2 as f16
__device__ __half g_fc1h[320 * 512];  // fc1_w as f16
__device__ __half g_fc2h[512];        // fc2_w as f16
__device__ uint4  g_comb4[512 * 40];  // comb [NG,320] as f16 (uint4-aligned)
__device__ float  g_sums[NG * 256];   // per-graph sums of h2
__device__ float  g_cnt[NG];          // per-graph node counts
__device__ float  g_ptab[25 * 8 * 64];// precomputed emb@conv_w table [tok][k][o]
__device__ float  g_prot[NG * 64];    // protein features after maxpool

// f16x8 reduction helper: p += v * nh (elementwise, 8 halves)
__device__ __forceinline__ void red_f16x8(__half* p, uint4 v, __half2 nh) {
    __half2 h0 = __hmul2(*(const __half2*)&v.x, nh);
    __half2 h1 = __hmul2(*(const __half2*)&v.y, nh);
    __half2 h2 = __hmul2(*(const __half2*)&v.z, nh);
    __half2 h3 = __hmul2(*(const __half2*)&v.w, nh);
    asm volatile("red.global.add.noftz.v4.f16x2 [%0], {%1,%2,%3,%4};"
                 :: "l"(p),
                    "r"(*(const unsigned int*)&h0), "r"(*(const unsigned int*)&h1),
                    "r"(*(const unsigned int*)&h2), "r"(*(const unsigned int*)&h3)
                 : "memory");
}

// 8 fp8(e4m3) packed in uint2 -> 8 f16 packed in uint4
__device__ __forceinline__ uint4 fp8x8_to_f16x8(uint2 qv) {
    uint4 r;
    __half2_raw a0 = __nv_cvt_fp8x2_to_halfraw2(
        (__nv_fp8x2_storage_t)(qv.x & 0xFFFF), __NV_E4M3);
    __half2_raw a1 = __nv_cvt_fp8x2_to_halfraw2(
        (__nv_fp8x2_storage_t)(qv.x >> 16), __NV_E4M3);
    __half2_raw a2 = __nv_cvt_fp8x2_to_halfraw2(
        (__nv_fp8x2_storage_t)(qv.y & 0xFFFF), __NV_E4M3);
    __half2_raw a3 = __nv_cvt_fp8x2_to_halfraw2(
        (__nv_fp8x2_storage_t)(qv.y >> 16), __NV_E4M3);
    r.x = *(unsigned int*)&a0;
    r.y = *(unsigned int*)&a1;
    r.z = *(unsigned int*)&a2;
    r.w = *(unsigned int*)&a3;
    return r;
}

// ---------------- zero + degree count ----------------------------------------
__global__ void k_zero(float* __restrict__ out, const float* __restrict__ fc2_b) {
    int t = blockIdx.x * blockDim.x + threadIdx.x;
    int stride = gridDim.x * blockDim.x;
    for (int i = t; i < NN; i += stride) g_cnti[i] = 0;
    for (int i = t; i < NG * 256; i += stride) g_sums[i] = 0.f;
    for (int i = t; i < NG; i += stride) { g_cnt[i] = 0.f; out[i] = fc2_b[0]; }
}

__global__ void k_deg(const int* __restrict__ dst) {
    int t = blockIdx.x * blockDim.x + threadIdx.x;
    if (t < NE) atomicAdd(&g_cnti[dst[t]], 1);
}

// init (grid = NE threads):
//  t < NN*10 : x16 = f16(x) padded; agg1 = f16(x/deg); inv per node; graph cnt
//  t < NE    : emeta[t] = {src, dst, rsqrt(deg_s)*rsqrt(deg_d), 0}
__global__ void k_init1(const float* __restrict__ x,
                        const int* __restrict__ batch,
                        const int* __restrict__ src,
                        const int* __restrict__ dst) {
    int t = blockIdx.x * blockDim.x + threadIdx.x;
    if (t < NN * 10) {
        int i = t / 10;
        int q = t - i * 10;
        float d = (float)g_cnti[i] + 1.0f;
        float inv = 1.0f / d;
        if (q == 0) {
            g_inv[i] = inv;
            atomicAdd(&g_cnt[batch[i]], 1.0f);
        }
        float v[8];
        if (q < 9) {
            const float2* xp = (const float2*)(x + (long)i * 78 + q * 8);
#pragma unroll
            for (int j = 0; j < 4; j++) {
                float2 a = xp[j];
                v[2 * j] = a.x; v[2 * j + 1] = a.y;
            }
        } else {
            const float2* xp = (const float2*)(x + (long)i * 78 + 72);
#pragma unroll
            for (int j = 0; j < 3; j++) {
                float2 a = xp[j];
                v[2 * j] = a.x; v[2 * j + 1] = a.y;
            }
            v[6] = 0.f; v[7] = 0.f;
        }
        uint4 raw, agg;
        __half2* rp = (__half2*)&raw;
        __half2* ap = (__half2*)&agg;
#pragma unroll
        for (int j = 0; j < 4; j++) {
            rp[j] = __floats2half2_rn(v[2 * j], v[2 * j + 1]);
            ap[j] = __floats2half2_rn(v[2 * j] * inv, v[2 * j + 1] * inv);
        }
        g_x16v[(long)i * 10 + q] = raw;
        g_agg1v[(long)i * 10 + q] = agg;
    }
    if (t < NE) {
        int s = __ldg(src + t), d = __ldg(dst + t);
        float nrm = rsqrtf((float)__ldg(g_cnti + s) + 1.0f) *
                    rsqrtf((float)__ldg(g_cnti + d) + 1.0f);
        g_emeta[t] = make_float4(__int_as_float(s), __int_as_float(d), nrm, 0.f);
    }
}

// ---------------- edge scatter, layer 1 (f16, flat chunk space) -------------
// one 16B emeta broadcast load per edge replaces 4 scalar meta loads.
__global__ void k_scatter1() {
    const int W = 2048 * 8;                 // total warps
    const int EPW = (NE + W - 1) / W;       // 98 edges per warp
    int w = (blockIdx.x * blockDim.x + threadIdx.x) >> 5;
    int lane = threadIdx.x & 31;
    int e0 = w * EPW;
    if (e0 >= NE) return;
    int ecnt = min(EPW, NE - e0);
    int nchunk = ecnt * 10;
    __half* agg = (__half*)g_agg1v;

    int c = lane;
    for (; c + 32 < nchunk; c += 64) {
        int c0 = c, c1 = c + 32;
        int le0 = c0 / 10, q0 = c0 - le0 * 10;
        int le1 = c1 / 10, q1 = c1 - le1 * 10;
        float4 m0 = __ldg(g_emeta + e0 + le0);
        float4 m1 = __ldg(g_emeta + e0 + le1);
        int s0 = __float_as_int(m0.x), d0 = __float_as_int(m0.y);
        int s1 = __float_as_int(m1.x), d1 = __float_as_int(m1.y);
        uint4 v0 = g_x16v[(long)s0 * 10 + q0];
        uint4 v1 = g_x16v[(long)s1 * 10 + q1];
        red_f16x8(agg + (long)d0 * 80 + q0 * 8, v0, __float2half2_rn(m0.z));
        red_f16x8(agg + (long)d1 * 80 + q1 * 8, v1, __float2half2_rn(m1.z));
    }
    for (; c < nchunk; c += 32) {
        int le = c / 10, q = c - le * 10;
        float4 m = __ldg(g_emeta + e0 + le);
        int s = __float_as_int(m.x), d = __float_as_int(m.y);
        uint4 v = g_x16v[(long)s * 10 + q];
        red_f16x8(agg + (long)d * 80 + q * 8, v, __float2half2_rn(m.z));
    }
}

// ---------------- prep: weights to f16 + emb@conv_w table (merged) ----------
__global__ void k_prep(const float* __restrict__ W1,
                       const float* __restrict__ W2,
                       const float* __restrict__ fc1_w,
                       const float* __restrict__ fc2_w,
                       const float* __restrict__ emb,
                       const float* __restrict__ conv_w) {
    int t = blockIdx.x * blockDim.x + threadIdx.x;
    if (t < 80 * 128) {
        int k = t >> 7;
        g_w1h[t] = __float2half((k < 78) ? W1[t] : 0.f);
    }
    if (t < 128 * 256) {
        g_w2h[t] = __float2half(W2[t]);
    }
    if (t < 320 * 512) {
        g_fc1h[t] = __float2half(fc1_w[t]);
    }
    if (t < 512) {
        g_fc2h[t] = __float2half(fc2_w[t]);
    }
    if (t < 25 * 8 * 64) {
        int o = t & 63;
        int k = (t >> 6) & 7;
        int tok = t >> 9;
        float s = 0.f;
#pragma unroll 4
        for (int i = 0; i < 128; i++)
            s += emb[tok * 128 + i] * conv_w[o * 1024 + i * 8 + k];
        g_ptab[tok * 512 + k * 64 + o] = s;
    }
}

// ---------------- GEMM1 (tensor cores): h1=relu(agg1@W1+b1) (fp8); agg2=h1/deg
__global__ __launch_bounds__(256) void k_gemm1(const float* __restrict__ b1) {
    __shared__ union {
        struct {
            uint4 a[128 * 11];   // f16 [128][88]
            uint4 b[80 * 17];    // f16 [80][136]
        } ld;
        float stg[128 * 68];
    } sm;
    int tid = threadIdx.x;
    int r0 = blockIdx.x * 128;
    int wid = tid >> 5;
    int wm = wid >> 1;      // 0..3
    int wn = wid & 1;       // 0..1

    const uint4 zero4 = make_uint4(0, 0, 0, 0);
    for (int idx = tid; idx < 128 * 10; idx += 256) {
        int r = idx / 10, u = idx - r * 10;
        int row = r0 + r;
        sm.ld.a[r * 11 + u] = (row < NN) ? g_agg1v[(long)row * 10 + u] : zero4;
    }
    const uint4* w1v = (const uint4*)g_w1h;
    for (int idx = tid; idx < 80 * 16; idx += 256) {
        int k = idx >> 4, u = idx & 15;
        sm.ld.b[k * 17 + u] = w1v[k * 16 + u];
    }
    __syncthreads();

    wmma::fragment<wmma::accumulator, 16, 16, 16, float> cf[2][4];
#pragma unroll
    for (int i = 0; i < 2; i++)
#pragma unroll
        for (int j = 0; j < 4; j++) wmma::fill_fragment(cf[i][j], 0.f);

    const __half* As = (const __half*)sm.ld.a;
    const __half* Bs = (const __half*)sm.ld.b;
#pragma unroll
    for (int k = 0; k < 80; k += 16) {
        wmma::fragment<wmma::matrix_a, 16, 16, 16, __half, wmma::row_major> af[2];
        wmma::load_matrix_sync(af[0], As + (wm * 32) * 88 + k, 88);
        wmma::load_matrix_sync(af[1], As + (wm * 32 + 16) * 88 + k, 88);
        wmma::fragment<wmma::matrix_b, 16, 16, 16, __half, wmma::row_major> bf[4];
#pragma unroll
        for (int j = 0; j < 4; j++)
            wmma::load_matrix_sync(bf[j], Bs + k * 136 + wn * 64 + j * 16, 136);
#pragma unroll
        for (int i = 0; i < 2; i++)
#pragma unroll
            for (int j = 0; j < 4; j++)
                wmma::mma_sync(cf[i][j], af[i], bf[j], cf[i][j]);
    }
    __syncthreads();

    unsigned short* h1q = (unsigned short*)g_h1qv;
    __half* a2 = (__half*)g_agg2v;
#pragma unroll 1
    for (int ph = 0; ph < 2; ph++) {
        if (wn == ph) {
#pragma unroll
            for (int i = 0; i < 2; i++)
#pragma unroll
                for (int j = 0; j < 4; j++)
                    wmma::store_matrix_sync(
                        sm.stg + (wm * 32 + i * 16) * 68 + j * 16,
                        cf[i][j], 68, wmma::mem_row_major);
        }
        __syncthreads();
        for (int idx = tid; idx < 128 * 32; idx += 256) {
            int r = idx >> 5;
            int cp = idx & 31;
            int row = r0 + r;
            if (row < NN) {
                int col = ph * 64 + cp * 2;          // global column
                float v0 = sm.stg[r * 68 + cp * 2];  // local read
                float v1 = sm.stg[r * 68 + cp * 2 + 1];
                v0 = fmaxf(v0 + b1[col], 0.f);
                v1 = fmaxf(v1 + b1[col + 1], 0.f);
                float inv = __ldg(g_inv + row);
                __nv_fp8x2_e4m3 q2(make_float2(v0, v1));
                h1q[(long)row * 64 + (col >> 1)] = (unsigned short)q2.__x;
                *(__half2*)(a2 + (long)row * 128 + col) =
                    __floats2half2_rn(v0 * inv, v1 * inv);
            }
        }
        __syncthreads();
    }
}

// ---------------- edge scatter, layer 2 (fp8 read, f16 RED) -----------------
__global__ void k_scatter2() {
    const int W = 2048 * 8;
    const int EPW = (NE + W - 1) / W;       // 98
    int w = (blockIdx.x * blockDim.x + threadIdx.x) >> 5;
    int lane = threadIdx.x & 31;
    int half = lane >> 4;
    int q = lane & 15;
    int e = w * EPW;
    int end = min(e + EPW, NE);
    if (e >= NE) return;
    __half* agg = (__half*)g_agg2v;

    for (; e + 3 < end; e += 4) {
        float4 ma = __ldg(g_emeta + e + half);
        float4 mb = __ldg(g_emeta + e + 2 + half);
        int sa = __float_as_int(ma.x), da = __float_as_int(ma.y);
        int sb = __float_as_int(mb.x), db = __float_as_int(mb.y);
        uint2 qa = g_h1qv[(long)sa * 16 + q];
        uint2 qb = g_h1qv[(long)sb * 16 + q];
        uint4 va = fp8x8_to_f16x8(qa);
        uint4 vb = fp8x8_to_f16x8(qb);
        red_f16x8(agg + (long)da * 128 + q * 8, va, __float2half2_rn(ma.z));
        red_f16x8(agg + (long)db * 128 + q * 8, vb, __float2half2_rn(mb.z));
    }
    for (; e < end; e += 2) {
        if (e + half < end) {
            float4 m = __ldg(g_emeta + e + half);
            int s = __float_as_int(m.x), d = __float_as_int(m.y);
            uint2 qv = g_h1qv[(long)s * 16 + q];
            uint4 v = fp8x8_to_f16x8(qv);
            red_f16x8(agg + (long)d * 128 + q * 8, v, __float2half2_rn(m.z));
        }
    }
}

// ---------------- GEMM2 (tensor cores) + fused mean-pool epilogue -----------
__global__ __launch_bounds__(256) void k_gemm2(const float* __restrict__ b2,
                                               const int* __restrict__ batch) {
    __shared__ union {
        struct {
            uint4 a[128 * 9];    // f16 [128][72] (K chunk 64)
            uint4 b[64 * 17];    // f16 [64][136]
        } ld;
        float stg[128 * 68];
    } sm;
    int tid = threadIdx.x;
    int r0 = blockIdx.x * 128;
    int cb = blockIdx.y * 128;
    int wid = tid >> 5;
    int wm = wid >> 1;
    int wn = wid & 1;

    wmma::fragment<wmma::accumulator, 16, 16, 16, float> cf[2][4];
#pragma unroll
    for (int i = 0; i < 2; i++)
#pragma unroll
        for (int j = 0; j < 4; j++) wmma::fill_fragment(cf[i][j], 0.f);

    const uint4 zero4 = make_uint4(0, 0, 0, 0);
    const uint4* w2v = (const uint4*)g_w2h;   // rows of 32 uint4 (256 halves)
    const __half* As = (const __half*)sm.ld.a;
    const __half* Bs = (const __half*)sm.ld.b;

#pragma unroll 1
    for (int kc = 0; kc < 128; kc += 64) {
        __syncthreads();
        for (int idx = tid; idx < 128 * 8; idx += 256) {
            int r = idx >> 3, u = idx & 7;
            int row = r0 + r;
            sm.ld.a[r * 9 + u] =
                (row < NN) ? g_agg2v[(long)row * 16 + (kc >> 3) + u] : zero4;
        }
        for (int idx = tid; idx < 64 * 16; idx += 256) {
            int k = idx >> 4, u = idx & 15;
            sm.ld.b[k * 17 + u] = w2v[(kc + k) * 32 + (cb >> 3) + u];
        }
        __syncthreads();
#pragma unroll
        for (int k = 0; k < 64; k += 16) {
            wmma::fragment<wmma::matrix_a, 16, 16, 16, __half, wmma::row_major> af[2];
            wmma::load_matrix_sync(af[0], As + (wm * 32) * 72 + k, 72);
            wmma::load_matrix_sync(af[1], As + (wm * 32 + 16) * 72 + k, 72);
            wmma::fragment<wmma::matrix_b, 16, 16, 16, __half, wmma::row_major> bf[4];
#pragma unroll
            for (int j = 0; j < 4; j++)
                wmma::load_matrix_sync(bf[j], Bs + k * 136 + wn * 64 + j * 16, 136);
#pragma unroll
            for (int i = 0; i < 2; i++)
#pragma unroll
                for (int j = 0; j < 4; j++)
                    wmma::mma_sync(cf[i][j], af[i], bf[j], cf[i][j]);
        }
    }
    __syncthreads();

#pragma unroll 1
    for (int ph = 0; ph < 2; ph++) {
        if (wn == ph) {
#pragma unroll
            for (int i = 0; i < 2; i++)
#pragma unroll
                for (int j = 0; j < 4; j++)
                    wmma::store_matrix_sync(
                        sm.stg + (wm * 32 + i * 16) * 68 + j * 16,
                        cf[i][j], 68, wmma::mem_row_major);
        }
        __syncthreads();
        for (int idx = tid; idx < 128 * 16; idx += 256) {
            int r = idx >> 4;
            int qd = idx & 15;
            int row = r0 + r;
            if (row < NN) {
                int lcol = qd * 4;                   // local staged column
                int gcol = cb + ph * 64 + lcol;      // global output column
                float v0 = fmaxf(sm.stg[r * 68 + lcol + 0] + b2[gcol + 0], 0.f);
                float v1 = fmaxf(sm.stg[r * 68 + lcol + 1] + b2[gcol + 1], 0.f);
                float v2 = fmaxf(sm.stg[r * 68 + lcol + 2] + b2[gcol + 2], 0.f);
                float v3 = fmaxf(sm.stg[r * 68 + lcol + 3] + b2[gcol + 3], 0.f);
                int g = __ldg(batch + row);
                float* p = g_sums + g * 256 + gcol;
                asm volatile("red.global.add.v4.f32 [%0], {%1,%2,%3,%4};"
                             :: "l"(p), "f"(v0), "f"(v1), "f"(v2), "f"(v3)
                             : "memory");
            }
        }
        __syncthreads();
    }
}

// ---------------- protein conv ------------------------------------------------
__global__ __launch_bounds__(256) void k_conv(const int* __restrict__ seq,
                                              const float* __restrict__ conv_b) {
    __shared__ float2 stab[25 * 8 * 16];   // [tok][k][chan-pair]
    __shared__ int sseq[1024];
    __shared__ float2 sred[256];
    int tid = threadIdx.x;
    int b = blockIdx.x;
    int co = blockIdx.y * 32;

    for (int idx = tid; idx < 1024; idx += 256) sseq[idx] = seq[b * 1024 + idx];
    for (int idx = tid; idx < 25 * 8 * 16; idx += 256) {
        int p = idx & 15;
        int kk = (idx >> 4) & 7;
        int tok = idx >> 7;
        stab[idx] = make_float2(g_ptab[tok * 512 + kk * 64 + co + 2 * p],
                                g_ptab[tok * 512 + kk * 64 + co + 2 * p + 1]);
    }
    __syncthreads();

    int p = tid & 15;
    int phase = tid >> 4;
    float2 m = make_float2(-1e30f, -1e30f);
    for (int l = phase; l < 1017; l += 16) {
        float sx = 0.f, sy = 0.f;
#pragma unroll
        for (int k = 0; k < 8; k++) {
            float2 v = stab[(sseq[l + k] * 8 + k) * 16 + p];
            sx += v.x; sy += v.y;
        }
        m.x = fmaxf(m.x, sx);
        m.y = fmaxf(m.y, sy);
    }
    sred[tid] = m;
    __syncthreads();
    if (tid < 16) {
        float2 mm = sred[tid];
#pragma unroll
        for (int g = 1; g < 16; g++) {
            float2 v = sred[g * 16 + tid];
            mm.x = fmaxf(mm.x, v.x);
            mm.y = fmaxf(mm.y, v.y);
        }
        g_prot[b * 64 + co + 2 * tid]     = fmaxf(mm.x + conv_b[co + 2 * tid], 0.f);
        g_prot[b * 64 + co + 2 * tid + 1] = fmaxf(mm.y + conv_b[co + 2 * tid + 1], 0.f);
    }
}

// ---------------- build comb [NG,320] f16 -------------------------------------
__global__ void k_comb() {
    int t = blockIdx.x * blockDim.x + threadIdx.x;
    if (t < NG * 320) {
        int g = t / 320;
        int j = t - g * 320;
        float invc = 1.0f / fmaxf(g_cnt[g], 1.0f);
        float v = (j < 256) ? g_sums[g * 256 + j] * invc
                            : g_prot[g * 64 + (j - 256)];
        ((__half*)g_comb4)[t] = __float2half(v);
    }
}

// ---------------- final MLP as tensor-core GEMM ------------------------------
__global__ __launch_bounds__(256) void k_gemmf(const float* __restrict__ fc1_b,
                                               float* __restrict__ out) {
    __shared__ union {
        struct {
            uint4 a[128 * 9];    // f16 [128][72] (K chunk 64)
            uint4 b[64 * 17];    // f16 [64][136]
        } ld;
        float stg[128 * 68];
    } sm;
    __shared__ float rowsum[128];
    int tid = threadIdx.x;
    int r0 = blockIdx.x * 128;
    int cb = blockIdx.y * 128;
    int wid = tid >> 5;
    int wm = wid >> 1;
    int wn = wid & 1;

    wmma::fragment<wmma::accumulator, 16, 16, 16, float> cf[2][4];
#pragma unroll
    for (int i = 0; i < 2; i++)
#pragma unroll
        for (int j = 0; j < 4; j++) wmma::fill_fragment(cf[i][j], 0.f);

    const uint4* av = g_comb4;                // row stride 40 uint4 (320 halves)
    const uint4* bv = (const uint4*)g_fc1h;   // row stride 64 uint4 (512 halves)
    const __half* As = (const __half*)sm.ld.a;
    const __half* Bs = (const __half*)sm.ld.b;

#pragma unroll 1
    for (int kc = 0; kc < 320; kc += 64) {
        __syncthreads();
        for (int idx = tid; idx < 128 * 8; idx += 256) {
            int r = idx >> 3, u = idx & 7;
            sm.ld.a[r * 9 + u] = av[(r0 + r) * 40 + (kc >> 3) + u];
        }
        for (int idx = tid; idx < 64 * 16; idx += 256) {
            int k = idx >> 4, u = idx & 15;
            sm.ld.b[k * 17 + u] = bv[(kc + k) * 64 + (cb >> 3) + u];
        }
        __syncthreads();
#pragma unroll
        for (int k = 0; k < 64; k += 16) {
            wmma::fragment<wmma::matrix_a, 16, 16, 16, __half, wmma::row_major> af[2];
            wmma::load_matrix_sync(af[0], As + (wm * 32) * 72 + k, 72);
            wmma::load_matrix_sync(af[1], As + (wm * 32 + 16) * 72 + k, 72);
            wmma::fragment<wmma::matrix_b, 16, 16, 16, __half, wmma::row_major> bf[4];
#pragma unroll
            for (int j = 0; j < 4; j++)
                wmma::load_matrix_sync(bf[j], Bs + k * 136 + wn * 64 + j * 16, 136);
#pragma unroll
            for (int i = 0; i < 2; i++)
#pragma unroll
                for (int j = 0; j < 4; j++)
                    wmma::mma_sync(cf[i][j], af[i], bf[j], cf[i][j]);
        }
    }
    __syncthreads();
    if (tid < 128) rowsum[tid] = 0.f;
    __syncthreads();

#pragma unroll 1
    for (int ph = 0; ph < 2; ph++) {
        if (wn == ph) {
#pragma unroll
            for (int i = 0; i < 2; i++)
#pragma unroll
                for (int j = 0; j < 4; j++)
                    wmma::store_matrix_sync(
                        sm.stg + (wm * 32 + i * 16) * 68 + j * 16,
                        cf[i][j], 68, wmma::mem_row_major);
        }
        __syncthreads();
        for (int idx = tid; idx < 128 * 16; idx += 256) {
            int r = idx >> 4;
            int qd = idx & 15;
            int lcol = qd * 4;
            int gcol = cb + ph * 64 + lcol;
            float p = 0.f;
#pragma unroll
            for (int i = 0; i < 4; i++) {
                float v = fmaxf(sm.stg[r * 68 + lcol + i] + fc1_b[gcol + i], 0.f);
                p += v * __half2float(g_fc2h[gcol + i]);
            }
            atomicAdd(&rowsum[r], p);
        }
        __syncthreads();
    }
    if (tid < 128) atomicAdd(&out[r0 + tid], rowsum[tid]);
}

// ---------------- launch ------------------------------------------------------
extern "C" void kernel_launch(void* const* d_in, const int* in_sizes, int n_in,
                              void* d_out, int out_size) {
    const float* x       = (const float*)d_in[0];
    const int*   ei      = (const int*)  d_in[1];   // [2, NE]
    const int*   batch   = (const int*)  d_in[2];
    const int*   seq     = (const int*)  d_in[3];   // [NG, 1024]
    const float* W1      = (const float*)d_in[4];
    const float* b1      = (const float*)d_in[5];
    const float* W2      = (const float*)d_in[6];
    const float* b2      = (const float*)d_in[7];
    const float* emb     = (const float*)d_in[8];
    const float* conv_w  = (const float*)d_in[9];
    const float* conv_b  = (const float*)d_in[10];
    const float* fc1_w   = (const float*)d_in[11];
    const float* fc1_b   = (const float*)d_in[12];
    const float* fc2_w   = (const float*)d_in[13];
    const float* fc2_b   = (const float*)d_in[14];
    float* out = (float*)d_out;

    const int* src = ei;
    const int* dst = ei + NE;

    k_zero<<<512, 256>>>(out, fc2_b);                         // 1
    k_deg<<<(NE + 255) / 256, 256>>>(dst);                    // 2
    k_init1<<<(NE + 255) / 256, 256>>>(x, batch, src, dst);   // 3
    k_scatter1<<<2048, 256>>>();                              // 4  <- profiled
    k_prep<<<(320 * 512 + 255) / 256, 256>>>(W1, W2, fc1_w, fc2_w,
                                             emb, conv_w);    // 5
    k_gemm1<<<(NN + 127) / 128, 256>>>(b1);                   // 6
    k_scatter2<<<2048, 256>>>();                              // 7
    {
        dim3 grid((NN + 127) / 128, 2);
        k_gemm2<<<grid, 256>>>(b2, batch);                    // 8
    }
    {
        dim3 grid(NG, 2);
        k_conv<<<grid, 256>>>(seq, conv_b);                   // 9
    }
    k_comb<<<(NG * 320 + 255) / 256, 256>>>();                // 10
    {
        dim3 grid(4, 4);
        k_gemmf<<<grid, 256>>>(fc1_b, out);                   // 11
    }
}

// round 15
// speedup vs baseline: 1.4367x; 1.0380x over previous
#include <cuda_runtime.h>
#include <cuda_fp16.h>
#include <cuda_fp8.h>
#include <mma.h>

using namespace nvcuda;

#define NN 100000
#define NE 1600000
#define NG 512

// ---------------- scratch (device globals; no allocations allowed) ----------
__device__ int    g_cnti[NN];         // int in-degree counts (deg = cnti + 1)
__device__ float  g_inv[NN];          // 1/deg
__device__ float4 g_emeta[NE];        // per-edge {src, dst, norm, pad}
__device__ uint4  g_x16v[NN * 10];    // x as __half[NN*80] (cols 78,79 = 0)
__device__ uint4  g_agg1v[NN * 10];   // aggregated x as __half[NN*80]
__device__ uint2  g_h1qv[NN * 16];    // relu(gcn1) as fp8 e4m3 [NN*128]
__device__ uint4  g_agg2v[NN * 16];   // aggregated h1 as __half[NN*128]
__device__ __half g_w1h[80 * 128];    // W1 as f16, K padded to 80
__device__ __half g_w2h[128 * 256];   // W2 as f16
__device__ __half g_fc1h[320 * 512];  // fc1_w as f16
__device__ __half g_fc2h[512];        // fc2_w as f16
__device__ uint4  g_comb4[512 * 40];  // comb [NG,320] as f16 (uint4-aligned)
__device__ float  g_sums[NG * 256];   // per-graph sums of h2
__device__ float  g_cnt[NG];          // per-graph node counts
__device__ float  g_ptab[25 * 8 * 64];// precomputed emb@conv_w table [tok][k][o]
__device__ float  g_prot[NG * 64];    // protein features after maxpool

// f16x8 reduction helper: p += v * nh (elementwise, 8 halves)
__device__ __forceinline__ void red_f16x8(__half* p, uint4 v, __half2 nh) {
    __half2 h0 = __hmul2(*(const __half2*)&v.x, nh);
    __half2 h1 = __hmul2(*(const __half2*)&v.y, nh);
    __half2 h2 = __hmul2(*(const __half2*)&v.z, nh);
    __half2 h3 = __hmul2(*(const __half2*)&v.w, nh);
    asm volatile("red.global.add.noftz.v4.f16x2 [%0], {%1,%2,%3,%4};"
                 :: "l"(p),
                    "r"(*(const unsigned int*)&h0), "r"(*(const unsigned int*)&h1),
                    "r"(*(const unsigned int*)&h2), "r"(*(const unsigned int*)&h3)
                 : "memory");
}

// 8 fp8(e4m3) packed in uint2 -> 8 f16 packed in uint4
__device__ __forceinline__ uint4 fp8x8_to_f16x8(uint2 qv) {
    uint4 r;
    __half2_raw a0 = __nv_cvt_fp8x2_to_halfraw2(
        (__nv_fp8x2_storage_t)(qv.x & 0xFFFF), __NV_E4M3);
    __half2_raw a1 = __nv_cvt_fp8x2_to_halfraw2(
        (__nv_fp8x2_storage_t)(qv.x >> 16), __NV_E4M3);
    __half2_raw a2 = __nv_cvt_fp8x2_to_halfraw2(
        (__nv_fp8x2_storage_t)(qv.y & 0xFFFF), __NV_E4M3);
    __half2_raw a3 = __nv_cvt_fp8x2_to_halfraw2(
        (__nv_fp8x2_storage_t)(qv.y >> 16), __NV_E4M3);
    r.x = *(unsigned int*)&a0;
    r.y = *(unsigned int*)&a1;
    r.z = *(unsigned int*)&a2;
    r.w = *(unsigned int*)&a3;
    return r;
}

// ---------------- zero + degree count ----------------------------------------
__global__ void k_zero(float* __restrict__ out, const float* __restrict__ fc2_b) {
    int t = blockIdx.x * blockDim.x + threadIdx.x;
    int stride = gridDim.x * blockDim.x;
    for (int i = t; i < NN; i += stride) g_cnti[i] = 0;
    for (int i = t; i < NG * 256; i += stride) g_sums[i] = 0.f;
    for (int i = t; i < NG; i += stride) { g_cnt[i] = 0.f; out[i] = fc2_b[0]; }
}

__global__ void k_deg(const int* __restrict__ dst) {
    int t = blockIdx.x * blockDim.x + threadIdx.x;
    if (t < NE) atomicAdd(&g_cnti[dst[t]], 1);
}

// init (grid = NE threads):
//  t < NN*10 : x16 = f16(x) padded; agg1 = f16(x/deg); inv per node; graph cnt
//  t < NE    : emeta[t] = {src, dst, rsqrt(deg_s)*rsqrt(deg_d), 0}
__global__ void k_init1(const float* __restrict__ x,
                        const int* __restrict__ batch,
                        const int* __restrict__ src,
                        const int* __restrict__ dst) {
    int t = blockIdx.x * blockDim.x + threadIdx.x;
    if (t < NN * 10) {
        int i = t / 10;
        int q = t - i * 10;
        float d = (float)g_cnti[i] + 1.0f;
        float inv = 1.0f / d;
        if (q == 0) {
            g_inv[i] = inv;
            atomicAdd(&g_cnt[batch[i]], 1.0f);
        }
        float v[8];
        if (q < 9) {
            const float2* xp = (const float2*)(x + (long)i * 78 + q * 8);
#pragma unroll
            for (int j = 0; j < 4; j++) {
                float2 a = xp[j];
                v[2 * j] = a.x; v[2 * j + 1] = a.y;
            }
        } else {
            const float2* xp = (const float2*)(x + (long)i * 78 + 72);
#pragma unroll
            for (int j = 0; j < 3; j++) {
                float2 a = xp[j];
                v[2 * j] = a.x; v[2 * j + 1] = a.y;
            }
            v[6] = 0.f; v[7] = 0.f;
        }
        uint4 raw, agg;
        __half2* rp = (__half2*)&raw;
        __half2* ap = (__half2*)&agg;
#pragma unroll
        for (int j = 0; j < 4; j++) {
            rp[j] = __floats2half2_rn(v[2 * j], v[2 * j + 1]);
            ap[j] = __floats2half2_rn(v[2 * j] * inv, v[2 * j + 1] * inv);
        }
        g_x16v[(long)i * 10 + q] = raw;
        g_agg1v[(long)i * 10 + q] = agg;
    }
    if (t < NE) {
        int s = __ldg(src + t), d = __ldg(dst + t);
        float nrm = rsqrtf((float)__ldg(g_cnti + s) + 1.0f) *
                    rsqrtf((float)__ldg(g_cnti + d) + 1.0f);
        g_emeta[t] = make_float4(__int_as_float(s), __int_as_float(d), nrm, 0.f);
    }
}

// ---------------- edge scatter, layer 1 (f16, flat chunk space) -------------
__global__ __launch_bounds__(256, 8) void k_scatter1() {
    const int W = 2048 * 8;                 // total warps
    const int EPW = (NE + W - 1) / W;       // 98 edges per warp
    int w = (blockIdx.x * blockDim.x + threadIdx.x) >> 5;
    int lane = threadIdx.x & 31;
    int e0 = w * EPW;
    if (e0 >= NE) return;
    int ecnt = min(EPW, NE - e0);
    int nchunk = ecnt * 10;
    __half* agg = (__half*)g_agg1v;

    int c = lane;
    for (; c + 32 < nchunk; c += 64) {
        int c0 = c, c1 = c + 32;
        int le0 = c0 / 10, q0 = c0 - le0 * 10;
        int le1 = c1 / 10, q1 = c1 - le1 * 10;
        float4 m0 = __ldg(g_emeta + e0 + le0);
        float4 m1 = __ldg(g_emeta + e0 + le1);
        int s0 = __float_as_int(m0.x), d0 = __float_as_int(m0.y);
        int s1 = __float_as_int(m1.x), d1 = __float_as_int(m1.y);
        uint4 v0 = g_x16v[(long)s0 * 10 + q0];
        uint4 v1 = g_x16v[(long)s1 * 10 + q1];
        red_f16x8(agg + (long)d0 * 80 + q0 * 8, v0, __float2half2_rn(m0.z));
        red_f16x8(agg + (long)d1 * 80 + q1 * 8, v1, __float2half2_rn(m1.z));
    }
    for (; c < nchunk; c += 32) {
        int le = c / 10, q = c - le * 10;
        float4 m = __ldg(g_emeta + e0 + le);
        int s = __float_as_int(m.x), d = __float_as_int(m.y);
        uint4 v = g_x16v[(long)s * 10 + q];
        red_f16x8(agg + (long)d * 80 + q * 8, v, __float2half2_rn(m.z));
    }
}

// ---------------- prep: weights to f16 + emb@conv_w table (merged) ----------
__global__ void k_prep(const float* __restrict__ W1,
                       const float* __restrict__ W2,
                       const float* __restrict__ fc1_w,
                       const float* __restrict__ fc2_w,
                       const float* __restrict__ emb,
                       const float* __restrict__ conv_w) {
    int t = blockIdx.x * blockDim.x + threadIdx.x;
    if (t < 80 * 128) {
        int k = t >> 7;
        g_w1h[t] = __float2half((k < 78) ? W1[t] : 0.f);
    }
    if (t < 128 * 256) {
        g_w2h[t] = __float2half(W2[t]);
    }
    if (t < 320 * 512) {
        g_fc1h[t] = __float2half(fc1_w[t]);
    }
    if (t < 512) {
        g_fc2h[t] = __float2half(fc2_w[t]);
    }
    if (t < 25 * 8 * 64) {
        int o = t & 63;
        int k = (t >> 6) & 7;
        int tok = t >> 9;
        float s = 0.f;
#pragma unroll 4
        for (int i = 0; i < 128; i++)
            s += emb[tok * 128 + i] * conv_w[o * 1024 + i * 8 + k];
        g_ptab[tok * 512 + k * 64 + o] = s;
    }
}

// ---------------- GEMM1 (tensor cores): h1=relu(agg1@W1+b1) (fp8); agg2=h1/deg
__global__ __launch_bounds__(256) void k_gemm1(const float* __restrict__ b1) {
    __shared__ union {
        struct {
            uint4 a[128 * 11];   // f16 [128][88]
            uint4 b[80 * 17];    // f16 [80][136]
        } ld;
        float stg[128 * 68];
    } sm;
    int tid = threadIdx.x;
    int r0 = blockIdx.x * 128;
    int wid = tid >> 5;
    int wm = wid >> 1;      // 0..3
    int wn = wid & 1;       // 0..1

    const uint4 zero4 = make_uint4(0, 0, 0, 0);
    for (int idx = tid; idx < 128 * 10; idx += 256) {
        int r = idx / 10, u = idx - r * 10;
        int row = r0 + r;
        sm.ld.a[r * 11 + u] = (row < NN) ? g_agg1v[(long)row * 10 + u] : zero4;
    }
    const uint4* w1v = (const uint4*)g_w1h;
    for (int idx = tid; idx < 80 * 16; idx += 256) {
        int k = idx >> 4, u = idx & 15;
        sm.ld.b[k * 17 + u] = w1v[k * 16 + u];
    }
    __syncthreads();

    wmma::fragment<wmma::accumulator, 16, 16, 16, float> cf[2][4];
#pragma unroll
    for (int i = 0; i < 2; i++)
#pragma unroll
        for (int j = 0; j < 4; j++) wmma::fill_fragment(cf[i][j], 0.f);

    const __half* As = (const __half*)sm.ld.a;
    const __half* Bs = (const __half*)sm.ld.b;
#pragma unroll
    for (int k = 0; k < 80; k += 16) {
        wmma::fragment<wmma::matrix_a, 16, 16, 16, __half, wmma::row_major> af[2];
        wmma::load_matrix_sync(af[0], As + (wm * 32) * 88 + k, 88);
        wmma::load_matrix_sync(af[1], As + (wm * 32 + 16) * 88 + k, 88);
        wmma::fragment<wmma::matrix_b, 16, 16, 16, __half, wmma::row_major> bf[4];
#pragma unroll
        for (int j = 0; j < 4; j++)
            wmma::load_matrix_sync(bf[j], Bs + k * 136 + wn * 64 + j * 16, 136);
#pragma unroll
        for (int i = 0; i < 2; i++)
#pragma unroll
            for (int j = 0; j < 4; j++)
                wmma::mma_sync(cf[i][j], af[i], bf[j], cf[i][j]);
    }
    __syncthreads();

    unsigned short* h1q = (unsigned short*)g_h1qv;
    __half* a2 = (__half*)g_agg2v;
#pragma unroll 1
    for (int ph = 0; ph < 2; ph++) {
        if (wn == ph) {
#pragma unroll
            for (int i = 0; i < 2; i++)
#pragma unroll
                for (int j = 0; j < 4; j++)
                    wmma::store_matrix_sync(
                        sm.stg + (wm * 32 + i * 16) * 68 + j * 16,
                        cf[i][j], 68, wmma::mem_row_major);
        }
        __syncthreads();
        for (int idx = tid; idx < 128 * 32; idx += 256) {
            int r = idx >> 5;
            int cp = idx & 31;
            int row = r0 + r;
            if (row < NN) {
                int col = ph * 64 + cp * 2;          // global column
                float v0 = sm.stg[r * 68 + cp * 2];  // local read
                float v1 = sm.stg[r * 68 + cp * 2 + 1];
                v0 = fmaxf(v0 + b1[col], 0.f);
                v1 = fmaxf(v1 + b1[col + 1], 0.f);
                float inv = __ldg(g_inv + row);
                __nv_fp8x2_e4m3 q2(make_float2(v0, v1));
                h1q[(long)row * 64 + (col >> 1)] = (unsigned short)q2.__x;
                *(__half2*)(a2 + (long)row * 128 + col) =
                    __floats2half2_rn(v0 * inv, v1 * inv);
            }
        }
        __syncthreads();
    }
}

// ---------------- edge scatter, layer 2 (fp8 read, f16 RED) -----------------
__global__ __launch_bounds__(256, 8) void k_scatter2() {
    const int W = 2048 * 8;
    const int EPW = (NE + W - 1) / W;       // 98
    int w = (blockIdx.x * blockDim.x + threadIdx.x) >> 5;
    int lane = threadIdx.x & 31;
    int half = lane >> 4;
    int q = lane & 15;
    int e = w * EPW;
    int end = min(e + EPW, NE);
    if (e >= NE) return;
    __half* agg = (__half*)g_agg2v;

    for (; e + 3 < end; e += 4) {
        float4 ma = __ldg(g_emeta + e + half);
        float4 mb = __ldg(g_emeta + e + 2 + half);
        int sa = __float_as_int(ma.x), da = __float_as_int(ma.y);
        int sb = __float_as_int(mb.x), db = __float_as_int(mb.y);
        uint2 qa = g_h1qv[(long)sa * 16 + q];
        uint2 qb = g_h1qv[(long)sb * 16 + q];
        uint4 va = fp8x8_to_f16x8(qa);
        uint4 vb = fp8x8_to_f16x8(qb);
        red_f16x8(agg + (long)da * 128 + q * 8, va, __float2half2_rn(ma.z));
        red_f16x8(agg + (long)db * 128 + q * 8, vb, __float2half2_rn(mb.z));
    }
    for (; e < end; e += 2) {
        if (e + half < end) {
            float4 m = __ldg(g_emeta + e + half);
            int s = __float_as_int(m.x), d = __float_as_int(m.y);
            uint2 qv = g_h1qv[(long)s * 16 + q];
            uint4 v = fp8x8_to_f16x8(qv);
            red_f16x8(agg + (long)d * 128 + q * 8, v, __float2half2_rn(m.z));
        }
    }
}

// ---------------- GEMM2 (tensor cores) + fused mean-pool epilogue -----------
__global__ __launch_bounds__(256) void k_gemm2(const float* __restrict__ b2,
                                               const int* __restrict__ batch) {
    __shared__ union {
        struct {
            uint4 a[128 * 9];    // f16 [128][72] (K chunk 64)
            uint4 b[64 * 17];    // f16 [64][136]
        } ld;
        float stg[128 * 68];
    } sm;
    int tid = threadIdx.x;
    int r0 = blockIdx.x * 128;
    int cb = blockIdx.y * 128;
    int wid = tid >> 5;
    int wm = wid >> 1;
    int wn = wid & 1;

    wmma::fragment<wmma::accumulator, 16, 16, 16, float> cf[2][4];
#pragma unroll
    for (int i = 0; i < 2; i++)
#pragma unroll
        for (int j = 0; j < 4; j++) wmma::fill_fragment(cf[i][j], 0.f);

    const uint4 zero4 = make_uint4(0, 0, 0, 0);
    const uint4* w2v = (const uint4*)g_w2h;   // rows of 32 uint4 (256 halves)
    const __half* As = (const __half*)sm.ld.a;
    const __half* Bs = (const __half*)sm.ld.b;

#pragma unroll 1
    for (int kc = 0; kc < 128; kc += 64) {
        __syncthreads();
        for (int idx = tid; idx < 128 * 8; idx += 256) {
            int r = idx >> 3, u = idx & 7;
            int row = r0 + r;
            sm.ld.a[r * 9 + u] =
                (row < NN) ? g_agg2v[(long)row * 16 + (kc >> 3) + u] : zero4;
        }
        for (int idx = tid; idx < 64 * 16; idx += 256) {
            int k = idx >> 4, u = idx & 15;
            sm.ld.b[k * 17 + u] = w2v[(kc + k) * 32 + (cb >> 3) + u];
        }
        __syncthreads();
#pragma unroll
        for (int k = 0; k < 64; k += 16) {
            wmma::fragment<wmma::matrix_a, 16, 16, 16, __half, wmma::row_major> af[2];
            wmma::load_matrix_sync(af[0], As + (wm * 32) * 72 + k, 72);
            wmma::load_matrix_sync(af[1], As + (wm * 32 + 16) * 72 + k, 72);
            wmma::fragment<wmma::matrix_b, 16, 16, 16, __half, wmma::row_major> bf[4];
#pragma unroll
            for (int j = 0; j < 4; j++)
                wmma::load_matrix_sync(bf[j], Bs + k * 136 + wn * 64 + j * 16, 136);
#pragma unroll
            for (int i = 0; i < 2; i++)
#pragma unroll
                for (int j = 0; j < 4; j++)
                    wmma::mma_sync(cf[i][j], af[i], bf[j], cf[i][j]);
        }
    }
    __syncthreads();

#pragma unroll 1
    for (int ph = 0; ph < 2; ph++) {
        if (wn == ph) {
#pragma unroll
            for (int i = 0; i < 2; i++)
#pragma unroll
                for (int j = 0; j < 4; j++)
                    wmma::store_matrix_sync(
                        sm.stg + (wm * 32 + i * 16) * 68 + j * 16,
                        cf[i][j], 68, wmma::mem_row_major);
        }
        __syncthreads();
        for (int idx = tid; idx < 128 * 16; idx += 256) {
            int r = idx >> 4;
            int qd = idx & 15;
            int row = r0 + r;
            if (row < NN) {
                int lcol = qd * 4;                   // local staged column
                int gcol = cb + ph * 64 + lcol;      // global output column
                float v0 = fmaxf(sm.stg[r * 68 + lcol + 0] + b2[gcol + 0], 0.f);
                float v1 = fmaxf(sm.stg[r * 68 + lcol + 1] + b2[gcol + 1], 0.f);
                float v2 = fmaxf(sm.stg[r * 68 + lcol + 2] + b2[gcol + 2], 0.f);
                float v3 = fmaxf(sm.stg[r * 68 + lcol + 3] + b2[gcol + 3], 0.f);
                int g = __ldg(batch + row);
                float* p = g_sums + g * 256 + gcol;
                asm volatile("red.global.add.v4.f32 [%0], {%1,%2,%3,%4};"
                             :: "l"(p), "f"(v0), "f"(v1), "f"(v2), "f"(v3)
                             : "memory");
            }
        }
        __syncthreads();
    }
}

// ---------------- protein conv ------------------------------------------------
__global__ __launch_bounds__(256) void k_conv(const int* __restrict__ seq,
                                              const float* __restrict__ conv_b) {
    __shared__ float2 stab[25 * 8 * 16];   // [tok][k][chan-pair]
    __shared__ int sseq[1024];
    __shared__ float2 sred[256];
    int tid = threadIdx.x;
    int b = blockIdx.x;
    int co = blockIdx.y * 32;

    for (int idx = tid; idx < 1024; idx += 256) sseq[idx] = seq[b * 1024 + idx];
    for (int idx = tid; idx < 25 * 8 * 16; idx += 256) {
        int p = idx & 15;
        int kk = (idx >> 4) & 7;
        int tok = idx >> 7;
        stab[idx] = make_float2(g_ptab[tok * 512 + kk * 64 + co + 2 * p],
                                g_ptab[tok * 512 + kk * 64 + co + 2 * p + 1]);
    }
    __syncthreads();

    int p = tid & 15;
    int phase = tid >> 4;
    float2 m = make_float2(-1e30f, -1e30f);
    for (int l = phase; l < 1017; l += 16) {
        float sx = 0.f, sy = 0.f;
#pragma unroll
        for (int k = 0; k < 8; k++) {
            float2 v = stab[(sseq[l + k] * 8 + k) * 16 + p];
            sx += v.x; sy += v.y;
        }
        m.x = fmaxf(m.x, sx);
        m.y = fmaxf(m.y, sy);
    }
    sred[tid] = m;
    __syncthreads();
    if (tid < 16) {
        float2 mm = sred[tid];
#pragma unroll
        for (int g = 1; g < 16; g++) {
            float2 v = sred[g * 16 + tid];
            mm.x = fmaxf(mm.x, v.x);
            mm.y = fmaxf(mm.y, v.y);
        }
        g_prot[b * 64 + co + 2 * tid]     = fmaxf(mm.x + conv_b[co + 2 * tid], 0.f);
        g_prot[b * 64 + co + 2 * tid + 1] = fmaxf(mm.y + conv_b[co + 2 * tid + 1], 0.f);
    }
}

// ---------------- build comb [NG,320] f16 -------------------------------------
__global__ void k_comb() {
    int t = blockIdx.x * blockDim.x + threadIdx.x;
    if (t < NG * 320) {
        int g = t / 320;
        int j = t - g * 320;
        float invc = 1.0f / fmaxf(g_cnt[g], 1.0f);
        float v = (j < 256) ? g_sums[g * 256 + j] * invc
                            : g_prot[g * 64 + (j - 256)];
        ((__half*)g_comb4)[t] = __float2half(v);
    }
}

// ---------------- final MLP as tensor-core GEMM ------------------------------
__global__ __launch_bounds__(256) void k_gemmf(const float* __restrict__ fc1_b,
                                               float* __restrict__ out) {
    __shared__ union {
        struct {
            uint4 a[128 * 9];    // f16 [128][72] (K chunk 64)
            uint4 b[64 * 17];    // f16 [64][136]
        } ld;
        float stg[128 * 68];
    } sm;
    __shared__ float rowsum[128];
    int tid = threadIdx.x;
    int r0 = blockIdx.x * 128;
    int cb = blockIdx.y * 128;
    int wid = tid >> 5;
    int wm = wid >> 1;
    int wn = wid & 1;

    wmma::fragment<wmma::accumulator, 16, 16, 16, float> cf[2][4];
#pragma unroll
    for (int i = 0; i < 2; i++)
#pragma unroll
        for (int j = 0; j < 4; j++) wmma::fill_fragment(cf[i][j], 0.f);

    const uint4* av = g_comb4;                // row stride 40 uint4 (320 halves)
    const uint4* bv = (const uint4*)g_fc1h;   // row stride 64 uint4 (512 halves)
    const __half* As = (const __half*)sm.ld.a;
    const __half* Bs = (const __half*)sm.ld.b;

#pragma unroll 1
    for (int kc = 0; kc < 320; kc += 64) {
        __syncthreads();
        for (int idx = tid; idx < 128 * 8; idx += 256) {
            int r = idx >> 3, u = idx & 7;
            sm.ld.a[r * 9 + u] = av[(r0 + r) * 40 + (kc >> 3) + u];
        }
        for (int idx = tid; idx < 64 * 16; idx += 256) {
            int k = idx >> 4, u = idx & 15;
            sm.ld.b[k * 17 + u] = bv[(kc + k) * 64 + (cb >> 3) + u];
        }
        __syncthreads();
#pragma unroll
        for (int k = 0; k < 64; k += 16) {
            wmma::fragment<wmma::matrix_a, 16, 16, 16, __half, wmma::row_major> af[2];
            wmma::load_matrix_sync(af[0], As + (wm * 32) * 72 + k, 72);
            wmma::load_matrix_sync(af[1], As + (wm * 32 + 16) * 72 + k, 72);
            wmma::fragment<wmma::matrix_b, 16, 16, 16, __half, wmma::row_major> bf[4];
#pragma unroll
            for (int j = 0; j < 4; j++)
                wmma::load_matrix_sync(bf[j], Bs + k * 136 + wn * 64 + j * 16, 136);
#pragma unroll
            for (int i = 0; i < 2; i++)
#pragma unroll
                for (int j = 0; j < 4; j++)
                    wmma::mma_sync(cf[i][j], af[i], bf[j], cf[i][j]);
        }
    }
    __syncthreads();
    if (tid < 128) rowsum[tid] = 0.f;
    __syncthreads();

#pragma unroll 1
    for (int ph = 0; ph < 2; ph++) {
        if (wn == ph) {
#pragma unroll
            for (int i = 0; i < 2; i++)
#pragma unroll
                for (int j = 0; j < 4; j++)
                    wmma::store_matrix_sync(
                        sm.stg + (wm * 32 + i * 16) * 68 + j * 16,
                        cf[i][j], 68, wmma::mem_row_major);
        }
        __syncthreads();
        for (int idx = tid; idx < 128 * 16; idx += 256) {
            int r = idx >> 4;
            int qd = idx & 15;
            int lcol = qd * 4;
            int gcol = cb + ph * 64 + lcol;
            float p = 0.f;
#pragma unroll
            for (int i = 0; i < 4; i++) {
                float v = fmaxf(sm.stg[r * 68 + lcol + i] + fc1_b[gcol + i], 0.f);
                p += v * __half2float(g_fc2h[gcol + i]);
            }
            atomicAdd(&rowsum[r], p);
        }
        __syncthreads();
    }
    if (tid < 128) atomicAdd(&out[r0 + tid], rowsum[tid]);
}

// ---------------- launch ------------------------------------------------------
extern "C" void kernel_launch(void* const* d_in, const int* in_sizes, int n_in,
                              void* d_out, int out_size) {
    const float* x       = (const float*)d_in[0];
    const int*   ei      = (const int*)  d_in[1];   // [2, NE]
    const int*   batch   = (const int*)  d_in[2];
    const int*   seq     = (const int*)  d_in[3];   // [NG, 1024]
    const float* W1      = (const float*)d_in[4];
    const float* b1      = (const float*)d_in[5];
    const float* W2      = (const float*)d_in[6];
    const float* b2      = (const float*)d_in[7];
    const float* emb     = (const float*)d_in[8];
    const float* conv_w  = (const float*)d_in[9];
    const float* conv_b  = (const float*)d_in[10];
    const float* fc1_w   = (const float*)d_in[11];
    const float* fc1_b   = (const float*)d_in[12];
    const float* fc2_w   = (const float*)d_in[13];
    const float* fc2_b   = (const float*)d_in[14];
    float* out = (float*)d_out;

    const int* src = ei;
    const int* dst = ei + NE;

    // side stream + events for the independent protein/weight-prep path
    static cudaStream_t s1 = nullptr;
    static cudaEvent_t evFork = nullptr, evPrep = nullptr, evConv = nullptr;
    if (s1 == nullptr) {
        cudaStreamCreateWithFlags(&s1, cudaStreamNonBlocking);
        cudaEventCreateWithFlags(&evFork, cudaEventDisableTiming);
        cudaEventCreateWithFlags(&evPrep, cudaEventDisableTiming);
        cudaEventCreateWithFlags(&evConv, cudaEventDisableTiming);
    }

    k_zero<<<512, 256>>>(out, fc2_b);                         // launch 1
    cudaEventRecord(evFork, 0);
    k_deg<<<(NE + 255) / 256, 256>>>(dst);                    // 2
    k_init1<<<(NE + 255) / 256, 256>>>(x, batch, src, dst);   // 3
    k_scatter1<<<2048, 256>>>();                              // 4  <- profiled

    // side stream: prep + conv, concurrent with deg/init1/scatter1
    cudaStreamWaitEvent(s1, evFork, 0);
    k_prep<<<(320 * 512 + 255) / 256, 256, 0, s1>>>(W1, W2, fc1_w, fc2_w,
                                                    emb, conv_w);
    cudaEventRecord(evPrep, s1);
    {
        dim3 grid(NG, 2);
        k_conv<<<grid, 256, 0, s1>>>(seq, conv_b);
    }
    cudaEventRecord(evConv, s1);

    cudaStreamWaitEvent(0, evPrep, 0);                        // gemm1 needs w1h
    k_gemm1<<<(NN + 127) / 128, 256>>>(b1);
    k_scatter2<<<2048, 256>>>();
    {
        dim3 grid((NN + 127) / 128, 2);
        k_gemm2<<<grid, 256>>>(b2, batch);
    }
    cudaStreamWaitEvent(0, evConv, 0);                        // comb needs g_prot
    k_comb<<<(NG * 320 + 255) / 256, 256>>>();
    {
        dim3 grid(4, 4);
        k_gemmf<<<grid, 256>>>(fc1_b, out);
    }
}

// round 16
// speedup vs baseline: 1.4402x; 1.0025x over previous
#include <cuda_runtime.h>
#include <cuda_fp16.h>
#include <cuda_fp8.h>
#include <mma.h>

using namespace nvcuda;

#define NN 100000
#define NE 1600000
#define NG 512

// ---------------- scratch (device globals; no allocations allowed) ----------
__device__ int    g_cnti[NN];         // int in-degree counts (deg = cnti + 1)
__device__ float  g_inv[NN];          // 1/deg
__device__ float4 g_emeta[NE];        // per-edge {src, dst, norm, pad}
__device__ uint4  g_x16v[NN * 10];    // x as __half[NN*80] (cols 78,79 = 0)
__device__ uint4  g_agg1v[NN * 10];   // aggregated x as __half[NN*80]
__device__ uint2  g_h1qv[NN * 16];    // relu(gcn1) as fp8 e4m3 [NN*128]
__device__ uint4  g_agg2v[NN * 16];   // aggregated h1 as __half[NN*128]
__device__ __half g_w1h[80 * 128];    // W1 as f16, K padded to 80
__device__ __half g_w2h[128 * 256];   // W2 as f16
__device__ __half g_fc1h[320 * 512];  // fc1_w as f16
__device__ __half g_fc2h[512];        // fc2_w as f16
__device__ float  g_sums[NG * 256];   // per-graph sums of h2
__device__ float  g_cnt[NG];          // per-graph node counts
__device__ float  g_ptab[25 * 8 * 64];// precomputed emb@conv_w table [tok][k][o]
__device__ float  g_prot[NG * 64];    // protein features after maxpool

// f16x8 reduction helper: p += v * nh (elementwise, 8 halves)
__device__ __forceinline__ void red_f16x8(__half* p, uint4 v, __half2 nh) {
    __half2 h0 = __hmul2(*(const __half2*)&v.x, nh);
    __half2 h1 = __hmul2(*(const __half2*)&v.y, nh);
    __half2 h2 = __hmul2(*(const __half2*)&v.z, nh);
    __half2 h3 = __hmul2(*(const __half2*)&v.w, nh);
    asm volatile("red.global.add.noftz.v4.f16x2 [%0], {%1,%2,%3,%4};"
                 :: "l"(p),
                    "r"(*(const unsigned int*)&h0), "r"(*(const unsigned int*)&h1),
                    "r"(*(const unsigned int*)&h2), "r"(*(const unsigned int*)&h3)
                 : "memory");
}

// 8 fp8(e4m3) packed in uint2 -> 8 f16 packed in uint4
__device__ __forceinline__ uint4 fp8x8_to_f16x8(uint2 qv) {
    uint4 r;
    __half2_raw a0 = __nv_cvt_fp8x2_to_halfraw2(
        (__nv_fp8x2_storage_t)(qv.x & 0xFFFF), __NV_E4M3);
    __half2_raw a1 = __nv_cvt_fp8x2_to_halfraw2(
        (__nv_fp8x2_storage_t)(qv.x >> 16), __NV_E4M3);
    __half2_raw a2 = __nv_cvt_fp8x2_to_halfraw2(
        (__nv_fp8x2_storage_t)(qv.y & 0xFFFF), __NV_E4M3);
    __half2_raw a3 = __nv_cvt_fp8x2_to_halfraw2(
        (__nv_fp8x2_storage_t)(qv.y >> 16), __NV_E4M3);
    r.x = *(unsigned int*)&a0;
    r.y = *(unsigned int*)&a1;
    r.z = *(unsigned int*)&a2;
    r.w = *(unsigned int*)&a3;
    return r;
}

// ---------------- zero + degree count ----------------------------------------
__global__ void k_zero(float* __restrict__ out, const float* __restrict__ fc2_b) {
    int t = blockIdx.x * blockDim.x + threadIdx.x;
    int stride = gridDim.x * blockDim.x;
    for (int i = t; i < NN; i += stride) g_cnti[i] = 0;
    for (int i = t; i < NG * 256; i += stride) g_sums[i] = 0.f;
    for (int i = t; i < NG; i += stride) { g_cnt[i] = 0.f; out[i] = fc2_b[0]; }
}

__global__ void k_deg(const int* __restrict__ dst) {
    int t = blockIdx.x * blockDim.x + threadIdx.x;
    if (t < NE) atomicAdd(&g_cnti[dst[t]], 1);
}

// x f32 -> f16 padded to 80 cols (side stream; overlapped by k_deg)
__global__ void k_xconv(const float* __restrict__ x) {
    int t = blockIdx.x * blockDim.x + threadIdx.x;
    if (t < NN * 10) {
        int i = t / 10;
        int q = t - i * 10;
        float v[8];
        if (q < 9) {
            const float2* xp = (const float2*)(x + (long)i * 78 + q * 8);
#pragma unroll
            for (int j = 0; j < 4; j++) {
                float2 a = xp[j];
                v[2 * j] = a.x; v[2 * j + 1] = a.y;
            }
        } else {
            const float2* xp = (const float2*)(x + (long)i * 78 + 72);
#pragma unroll
            for (int j = 0; j < 3; j++) {
                float2 a = xp[j];
                v[2 * j] = a.x; v[2 * j + 1] = a.y;
            }
            v[6] = 0.f; v[7] = 0.f;
        }
        uint4 raw;
        __half2* rp = (__half2*)&raw;
#pragma unroll
        for (int j = 0; j < 4; j++)
            rp[j] = __floats2half2_rn(v[2 * j], v[2 * j + 1]);
        g_x16v[(long)i * 10 + q] = raw;
    }
}

// init (grid = NE threads):
//  t < NN*10 : agg1 = x16 * (1/deg) (f16); inv per node; graph cnt
//  t < NE    : emeta[t] = {src, dst, rsqrt(deg_s)*rsqrt(deg_d), 0}
__global__ void k_init1(const int* __restrict__ batch,
                        const int* __restrict__ src,
                        const int* __restrict__ dst) {
    int t = blockIdx.x * blockDim.x + threadIdx.x;
    if (t < NN * 10) {
        int i = t / 10;
        int q = t - i * 10;
        float d = (float)g_cnti[i] + 1.0f;
        float inv = 1.0f / d;
        if (q == 0) {
            g_inv[i] = inv;
            atomicAdd(&g_cnt[batch[i]], 1.0f);
        }
        uint4 raw = g_x16v[(long)i * 10 + q];
        __half2 invh = __float2half2_rn(inv);
        uint4 agg;
        __half2* rp = (__half2*)&raw;
        __half2* ap = (__half2*)&agg;
#pragma unroll
        for (int j = 0; j < 4; j++)
            ap[j] = __hmul2(rp[j], invh);
        g_agg1v[(long)i * 10 + q] = agg;
    }
    if (t < NE) {
        int s = __ldg(src + t), d = __ldg(dst + t);
        float nrm = rsqrtf((float)__ldg(g_cnti + s) + 1.0f) *
                    rsqrtf((float)__ldg(g_cnti + d) + 1.0f);
        g_emeta[t] = make_float4(__int_as_float(s), __int_as_float(d), nrm, 0.f);
    }
}

// ---------------- edge scatter, layer 1 (f16, flat chunk space) -------------
__global__ __launch_bounds__(256, 8) void k_scatter1() {
    const int W = 2048 * 8;                 // total warps
    const int EPW = (NE + W - 1) / W;       // 98 edges per warp
    int w = (blockIdx.x * blockDim.x + threadIdx.x) >> 5;
    int lane = threadIdx.x & 31;
    int e0 = w * EPW;
    if (e0 >= NE) return;
    int ecnt = min(EPW, NE - e0);
    int nchunk = ecnt * 10;
    __half* agg = (__half*)g_agg1v;

    int c = lane;
    for (; c + 32 < nchunk; c += 64) {
        int c0 = c, c1 = c + 32;
        int le0 = c0 / 10, q0 = c0 - le0 * 10;
        int le1 = c1 / 10, q1 = c1 - le1 * 10;
        float4 m0 = __ldg(g_emeta + e0 + le0);
        float4 m1 = __ldg(g_emeta + e0 + le1);
        int s0 = __float_as_int(m0.x), d0 = __float_as_int(m0.y);
        int s1 = __float_as_int(m1.x), d1 = __float_as_int(m1.y);
        uint4 v0 = g_x16v[(long)s0 * 10 + q0];
        uint4 v1 = g_x16v[(long)s1 * 10 + q1];
        red_f16x8(agg + (long)d0 * 80 + q0 * 8, v0, __float2half2_rn(m0.z));
        red_f16x8(agg + (long)d1 * 80 + q1 * 8, v1, __float2half2_rn(m1.z));
    }
    for (; c < nchunk; c += 32) {
        int le = c / 10, q = c - le * 10;
        float4 m = __ldg(g_emeta + e0 + le);
        int s = __float_as_int(m.x), d = __float_as_int(m.y);
        uint4 v = g_x16v[(long)s * 10 + q];
        red_f16x8(agg + (long)d * 80 + q * 8, v, __float2half2_rn(m.z));
    }
}

// ---------------- prep: weights to f16 + emb@conv_w table (merged) ----------
__global__ void k_prep(const float* __restrict__ W1,
                       const float* __restrict__ W2,
                       const float* __restrict__ fc1_w,
                       const float* __restrict__ fc2_w,
                       const float* __restrict__ emb,
                       const float* __restrict__ conv_w) {
    int t = blockIdx.x * blockDim.x + threadIdx.x;
    if (t < 80 * 128) {
        int k = t >> 7;
        g_w1h[t] = __float2half((k < 78) ? W1[t] : 0.f);
    }
    if (t < 128 * 256) {
        g_w2h[t] = __float2half(W2[t]);
    }
    if (t < 320 * 512) {
        g_fc1h[t] = __float2half(fc1_w[t]);
    }
    if (t < 512) {
        g_fc2h[t] = __float2half(fc2_w[t]);
    }
    if (t < 25 * 8 * 64) {
        int o = t & 63;
        int k = (t >> 6) & 7;
        int tok = t >> 9;
        float s = 0.f;
#pragma unroll 4
        for (int i = 0; i < 128; i++)
            s += emb[tok * 128 + i] * conv_w[o * 1024 + i * 8 + k];
        g_ptab[tok * 512 + k * 64 + o] = s;
    }
}

// ---------------- GEMM1 (tensor cores): h1=relu(agg1@W1+b1) (fp8); agg2=h1/deg
__global__ __launch_bounds__(256) void k_gemm1(const float* __restrict__ b1) {
    __shared__ union {
        struct {
            uint4 a[128 * 11];   // f16 [128][88]
            uint4 b[80 * 17];    // f16 [80][136]
        } ld;
        float stg[128 * 68];
    } sm;
    int tid = threadIdx.x;
    int r0 = blockIdx.x * 128;
    int wid = tid >> 5;
    int wm = wid >> 1;      // 0..3
    int wn = wid & 1;       // 0..1

    const uint4 zero4 = make_uint4(0, 0, 0, 0);
    for (int idx = tid; idx < 128 * 10; idx += 256) {
        int r = idx / 10, u = idx - r * 10;
        int row = r0 + r;
        sm.ld.a[r * 11 + u] = (row < NN) ? g_agg1v[(long)row * 10 + u] : zero4;
    }
    const uint4* w1v = (const uint4*)g_w1h;
    for (int idx = tid; idx < 80 * 16; idx += 256) {
        int k = idx >> 4, u = idx & 15;
        sm.ld.b[k * 17 + u] = w1v[k * 16 + u];
    }
    __syncthreads();

    wmma::fragment<wmma::accumulator, 16, 16, 16, float> cf[2][4];
#pragma unroll
    for (int i = 0; i < 2; i++)
#pragma unroll
        for (int j = 0; j < 4; j++) wmma::fill_fragment(cf[i][j], 0.f);

    const __half* As = (const __half*)sm.ld.a;
    const __half* Bs = (const __half*)sm.ld.b;
#pragma unroll
    for (int k = 0; k < 80; k += 16) {
        wmma::fragment<wmma::matrix_a, 16, 16, 16, __half, wmma::row_major> af[2];
        wmma::load_matrix_sync(af[0], As + (wm * 32) * 88 + k, 88);
        wmma::load_matrix_sync(af[1], As + (wm * 32 + 16) * 88 + k, 88);
        wmma::fragment<wmma::matrix_b, 16, 16, 16, __half, wmma::row_major> bf[4];
#pragma unroll
        for (int j = 0; j < 4; j++)
            wmma::load_matrix_sync(bf[j], Bs + k * 136 + wn * 64 + j * 16, 136);
#pragma unroll
        for (int i = 0; i < 2; i++)
#pragma unroll
            for (int j = 0; j < 4; j++)
                wmma::mma_sync(cf[i][j], af[i], bf[j], cf[i][j]);
    }
    __syncthreads();

    unsigned short* h1q = (unsigned short*)g_h1qv;
    __half* a2 = (__half*)g_agg2v;
#pragma unroll 1
    for (int ph = 0; ph < 2; ph++) {
        if (wn == ph) {
#pragma unroll
            for (int i = 0; i < 2; i++)
#pragma unroll
                for (int j = 0; j < 4; j++)
                    wmma::store_matrix_sync(
                        sm.stg + (wm * 32 + i * 16) * 68 + j * 16,
                        cf[i][j], 68, wmma::mem_row_major);
        }
        __syncthreads();
        for (int idx = tid; idx < 128 * 32; idx += 256) {
            int r = idx >> 5;
            int cp = idx & 31;
            int row = r0 + r;
            if (row < NN) {
                int col = ph * 64 + cp * 2;          // global column
                float v0 = sm.stg[r * 68 + cp * 2];  // local read
                float v1 = sm.stg[r * 68 + cp * 2 + 1];
                v0 = fmaxf(v0 + b1[col], 0.f);
                v1 = fmaxf(v1 + b1[col + 1], 0.f);
                float inv = __ldg(g_inv + row);
                __nv_fp8x2_e4m3 q2(make_float2(v0, v1));
                h1q[(long)row * 64 + (col >> 1)] = (unsigned short)q2.__x;
                *(__half2*)(a2 + (long)row * 128 + col) =
                    __floats2half2_rn(v0 * inv, v1 * inv);
            }
        }
        __syncthreads();
    }
}

// ---------------- edge scatter, layer 2 (fp8 read, f16 RED, 8 edges/iter) ---
__global__ __launch_bounds__(256) void k_scatter2() {
    const int W = 2048 * 8;
    const int EPW = (NE + W - 1) / W;       // 98
    int w = (blockIdx.x * blockDim.x + threadIdx.x) >> 5;
    int lane = threadIdx.x & 31;
    int half = lane >> 4;
    int q = lane & 15;
    int e = w * EPW;
    int end = min(e + EPW, NE);
    if (e >= NE) return;
    __half* agg = (__half*)g_agg2v;

    for (; e + 7 < end; e += 8) {
        float4 m0 = __ldg(g_emeta + e + half);
        float4 m1 = __ldg(g_emeta + e + 2 + half);
        float4 m2 = __ldg(g_emeta + e + 4 + half);
        float4 m3 = __ldg(g_emeta + e + 6 + half);
        uint2 q0 = g_h1qv[(long)__float_as_int(m0.x) * 16 + q];
        uint2 q1 = g_h1qv[(long)__float_as_int(m1.x) * 16 + q];
        uint2 q2 = g_h1qv[(long)__float_as_int(m2.x) * 16 + q];
        uint2 q3 = g_h1qv[(long)__float_as_int(m3.x) * 16 + q];
        red_f16x8(agg + (long)__float_as_int(m0.y) * 128 + q * 8,
                  fp8x8_to_f16x8(q0), __float2half2_rn(m0.z));
        red_f16x8(agg + (long)__float_as_int(m1.y) * 128 + q * 8,
                  fp8x8_to_f16x8(q1), __float2half2_rn(m1.z));
        red_f16x8(agg + (long)__float_as_int(m2.y) * 128 + q * 8,
                  fp8x8_to_f16x8(q2), __float2half2_rn(m2.z));
        red_f16x8(agg + (long)__float_as_int(m3.y) * 128 + q * 8,
                  fp8x8_to_f16x8(q3), __float2half2_rn(m3.z));
    }
    for (; e < end; e += 2) {
        if (e + half < end) {
            float4 m = __ldg(g_emeta + e + half);
            int s = __float_as_int(m.x), d = __float_as_int(m.y);
            uint2 qv = g_h1qv[(long)s * 16 + q];
            uint4 v = fp8x8_to_f16x8(qv);
            red_f16x8(agg + (long)d * 128 + q * 8, v, __float2half2_rn(m.z));
        }
    }
}

// ---------------- GEMM2 (tensor cores) + fused mean-pool epilogue -----------
__global__ __launch_bounds__(256) void k_gemm2(const float* __restrict__ b2,
                                               const int* __restrict__ batch) {
    __shared__ union {
        struct {
            uint4 a[128 * 9];    // f16 [128][72] (K chunk 64)
            uint4 b[64 * 17];    // f16 [64][136]
        } ld;
        float stg[128 * 68];
    } sm;
    int tid = threadIdx.x;
    int r0 = blockIdx.x * 128;
    int cb = blockIdx.y * 128;
    int wid = tid >> 5;
    int wm = wid >> 1;
    int wn = wid & 1;

    wmma::fragment<wmma::accumulator, 16, 16, 16, float> cf[2][4];
#pragma unroll
    for (int i = 0; i < 2; i++)
#pragma unroll
        for (int j = 0; j < 4; j++) wmma::fill_fragment(cf[i][j], 0.f);

    const uint4 zero4 = make_uint4(0, 0, 0, 0);
    const uint4* w2v = (const uint4*)g_w2h;   // rows of 32 uint4 (256 halves)
    const __half* As = (const __half*)sm.ld.a;
    const __half* Bs = (const __half*)sm.ld.b;

#pragma unroll 1
    for (int kc = 0; kc < 128; kc += 64) {
        __syncthreads();
        for (int idx = tid; idx < 128 * 8; idx += 256) {
            int r = idx >> 3, u = idx & 7;
            int row = r0 + r;
            sm.ld.a[r * 9 + u] =
                (row < NN) ? g_agg2v[(long)row * 16 + (kc >> 3) + u] : zero4;
        }
        for (int idx = tid; idx < 64 * 16; idx += 256) {
            int k = idx >> 4, u = idx & 15;
            sm.ld.b[k * 17 + u] = w2v[(kc + k) * 32 + (cb >> 3) + u];
        }
        __syncthreads();
#pragma unroll
        for (int k = 0; k < 64; k += 16) {
            wmma::fragment<wmma::matrix_a, 16, 16, 16, __half, wmma::row_major> af[2];
            wmma::load_matrix_sync(af[0], As + (wm * 32) * 72 + k, 72);
            wmma::load_matrix_sync(af[1], As + (wm * 32 + 16) * 72 + k, 72);
            wmma::fragment<wmma::matrix_b, 16, 16, 16, __half, wmma::row_major> bf[4];
#pragma unroll
            for (int j = 0; j < 4; j++)
                wmma::load_matrix_sync(bf[j], Bs + k * 136 + wn * 64 + j * 16, 136);
#pragma unroll
            for (int i = 0; i < 2; i++)
#pragma unroll
                for (int j = 0; j < 4; j++)
                    wmma::mma_sync(cf[i][j], af[i], bf[j], cf[i][j]);
        }
    }
    __syncthreads();

#pragma unroll 1
    for (int ph = 0; ph < 2; ph++) {
        if (wn == ph) {
#pragma unroll
            for (int i = 0; i < 2; i++)
#pragma unroll
                for (int j = 0; j < 4; j++)
                    wmma::store_matrix_sync(
                        sm.stg + (wm * 32 + i * 16) * 68 + j * 16,
                        cf[i][j], 68, wmma::mem_row_major);
        }
        __syncthreads();
        for (int idx = tid; idx < 128 * 16; idx += 256) {
            int r = idx >> 4;
            int qd = idx & 15;
            int row = r0 + r;
            if (row < NN) {
                int lcol = qd * 4;                   // local staged column
                int gcol = cb + ph * 64 + lcol;      // global output column
                float v0 = fmaxf(sm.stg[r * 68 + lcol + 0] + b2[gcol + 0], 0.f);
                float v1 = fmaxf(sm.stg[r * 68 + lcol + 1] + b2[gcol + 1], 0.f);
                float v2 = fmaxf(sm.stg[r * 68 + lcol + 2] + b2[gcol + 2], 0.f);
                float v3 = fmaxf(sm.stg[r * 68 + lcol + 3] + b2[gcol + 3], 0.f);
                int g = __ldg(batch + row);
                float* p = g_sums + g * 256 + gcol;
                asm volatile("red.global.add.v4.f32 [%0], {%1,%2,%3,%4};"
                             :: "l"(p), "f"(v0), "f"(v1), "f"(v2), "f"(v3)
                             : "memory");
            }
        }
        __syncthreads();
    }
}

// ---------------- protein conv ------------------------------------------------
__global__ __launch_bounds__(256) void k_conv(const int* __restrict__ seq,
                                              const float* __restrict__ conv_b) {
    __shared__ float2 stab[25 * 8 * 16];   // [tok][k][chan-pair]
    __shared__ int sseq[1024];
    __shared__ float2 sred[256];
    int tid = threadIdx.x;
    int b = blockIdx.x;
    int co = blockIdx.y * 32;

    for (int idx = tid; idx < 1024; idx += 256) sseq[idx] = seq[b * 1024 + idx];
    for (int idx = tid; idx < 25 * 8 * 16; idx += 256) {
        int p = idx & 15;
        int kk = (idx >> 4) & 7;
        int tok = idx >> 7;
        stab[idx] = make_float2(g_ptab[tok * 512 + kk * 64 + co + 2 * p],
                                g_ptab[tok * 512 + kk * 64 + co + 2 * p + 1]);
    }
    __syncthreads();

    int p = tid & 15;
    int phase = tid >> 4;
    float2 m = make_float2(-1e30f, -1e30f);
    for (int l = phase; l < 1017; l += 16) {
        float sx = 0.f, sy = 0.f;
#pragma unroll
        for (int k = 0; k < 8; k++) {
            float2 v = stab[(sseq[l + k] * 8 + k) * 16 + p];
            sx += v.x; sy += v.y;
        }
        m.x = fmaxf(m.x, sx);
        m.y = fmaxf(m.y, sy);
    }
    sred[tid] = m;
    __syncthreads();
    if (tid < 16) {
        float2 mm = sred[tid];
#pragma unroll
        for (int g = 1; g < 16; g++) {
            float2 v = sred[g * 16 + tid];
            mm.x = fmaxf(mm.x, v.x);
            mm.y = fmaxf(mm.y, v.y);
        }
        g_prot[b * 64 + co + 2 * tid]     = fmaxf(mm.x + conv_b[co + 2 * tid], 0.f);
        g_prot[b * 64 + co + 2 * tid + 1] = fmaxf(mm.y + conv_b[co + 2 * tid + 1], 0.f);
    }
}

// ---------------- final MLP as tensor-core GEMM (comb fused into A-load) -----
__global__ __launch_bounds__(256) void k_gemmf(const float* __restrict__ fc1_b,
                                               float* __restrict__ out) {
    __shared__ union {
        struct {
            uint4 a[128 * 9];    // f16 [128][72] (K chunk 64)
            uint4 b[64 * 17];    // f16 [64][136]
        } ld;
        float stg[128 * 68];
    } sm;
    __shared__ float rowsum[128];
    int tid = threadIdx.x;
    int r0 = blockIdx.x * 128;
    int cb = blockIdx.y * 128;
    int wid = tid >> 5;
    int wm = wid >> 1;
    int wn = wid & 1;

    wmma::fragment<wmma::accumulator, 16, 16, 16, float> cf[2][4];
#pragma unroll
    for (int i = 0; i < 2; i++)
#pragma unroll
        for (int j = 0; j < 4; j++) wmma::fill_fragment(cf[i][j], 0.f);

    const uint4* bv = (const uint4*)g_fc1h;   // row stride 64 uint4 (512 halves)
    const __half* As = (const __half*)sm.ld.a;
    const __half* Bs = (const __half*)sm.ld.b;

#pragma unroll 1
    for (int kc = 0; kc < 320; kc += 64) {
        __syncthreads();
        // A tile: comb[row][kc..kc+64) computed on the fly (f16)
        for (int idx = tid; idx < 128 * 8; idx += 256) {
            int r = idx >> 3, u = idx & 7;
            int row = r0 + r;                      // graph id
            int k0 = kc + u * 8;
            float invc = 1.0f / fmaxf(g_cnt[row], 1.0f);
            uint4 av;
            __half2* ap = (__half2*)&av;
#pragma unroll
            for (int j = 0; j < 4; j++) {
                int c0 = k0 + 2 * j, c1 = k0 + 2 * j + 1;
                float f0 = (c0 < 256) ? g_sums[row * 256 + c0] * invc
                                      : g_prot[row * 64 + (c0 - 256)];
                float f1 = (c1 < 256) ? g_sums[row * 256 + c1] * invc
                                      : g_prot[row * 64 + (c1 - 256)];
                ap[j] = __floats2half2_rn(f0, f1);
            }
            sm.ld.a[r * 9 + u] = av;
        }
        for (int idx = tid; idx < 64 * 16; idx += 256) {
            int k = idx >> 4, u = idx & 15;
            sm.ld.b[k * 17 + u] = bv[(kc + k) * 64 + (cb >> 3) + u];
        }
        __syncthreads();
#pragma unroll
        for (int k = 0; k < 64; k += 16) {
            wmma::fragment<wmma::matrix_a, 16, 16, 16, __half, wmma::row_major> af[2];
            wmma::load_matrix_sync(af[0], As + (wm * 32) * 72 + k, 72);
            wmma::load_matrix_sync(af[1], As + (wm * 32 + 16) * 72 + k, 72);
            wmma::fragment<wmma::matrix_b, 16, 16, 16, __half, wmma::row_major> bf[4];
#pragma unroll
            for (int j = 0; j < 4; j++)
                wmma::load_matrix_sync(bf[j], Bs + k * 136 + wn * 64 + j * 16, 136);
#pragma unroll
            for (int i = 0; i < 2; i++)
#pragma unroll
                for (int j = 0; j < 4; j++)
                    wmma::mma_sync(cf[i][j], af[i], bf[j], cf[i][j]);
        }
    }
    __syncthreads();
    if (tid < 128) rowsum[tid] = 0.f;
    __syncthreads();

#pragma unroll 1
    for (int ph = 0; ph < 2; ph++) {
        if (wn == ph) {
#pragma unroll
            for (int i = 0; i < 2; i++)
#pragma unroll
                for (int j = 0; j < 4; j++)
                    wmma::store_matrix_sync(
                        sm.stg + (wm * 32 + i * 16) * 68 + j * 16,
                        cf[i][j], 68, wmma::mem_row_major);
        }
        __syncthreads();
        for (int idx = tid; idx < 128 * 16; idx += 256) {
            int r = idx >> 4;
            int qd = idx & 15;
            int lcol = qd * 4;
            int gcol = cb + ph * 64 + lcol;
            float p = 0.f;
#pragma unroll
            for (int i = 0; i < 4; i++) {
                float v = fmaxf(sm.stg[r * 68 + lcol + i] + fc1_b[gcol + i], 0.f);
                p += v * __half2float(g_fc2h[gcol + i]);
            }
            atomicAdd(&rowsum[r], p);
        }
        __syncthreads();
    }
    if (tid < 128) atomicAdd(&out[r0 + tid], rowsum[tid]);
}

// ---------------- launch ------------------------------------------------------
extern "C" void kernel_launch(void* const* d_in, const int* in_sizes, int n_in,
                              void* d_out, int out_size) {
    const float* x       = (const float*)d_in[0];
    const int*   ei      = (const int*)  d_in[1];   // [2, NE]
    const int*   batch   = (const int*)  d_in[2];
    const int*   seq     = (const int*)  d_in[3];   // [NG, 1024]
    const float* W1      = (const float*)d_in[4];
    const float* b1      = (const float*)d_in[5];
    const float* W2      = (const float*)d_in[6];
    const float* b2      = (const float*)d_in[7];
    const float* emb     = (const float*)d_in[8];
    const float* conv_w  = (const float*)d_in[9];
    const float* conv_b  = (const float*)d_in[10];
    const float* fc1_w   = (const float*)d_in[11];
    const float* fc1_b   = (const float*)d_in[12];
    const float* fc2_w   = (const float*)d_in[13];
    const float* fc2_b   = (const float*)d_in[14];
    float* out = (float*)d_out;

    const int* src = ei;
    const int* dst = ei + NE;

    // side stream + events for independent work
    static cudaStream_t s1 = nullptr;
    static cudaEvent_t evFork = nullptr, evX = nullptr, evPrep = nullptr,
                       evConv = nullptr;
    if (s1 == nullptr) {
        cudaStreamCreateWithFlags(&s1, cudaStreamNonBlocking);
        cudaEventCreateWithFlags(&evFork, cudaEventDisableTiming);
        cudaEventCreateWithFlags(&evX, cudaEventDisableTiming);
        cudaEventCreateWithFlags(&evPrep, cudaEventDisableTiming);
        cudaEventCreateWithFlags(&evConv, cudaEventDisableTiming);
    }

    k_zero<<<512, 256>>>(out, fc2_b);                         // launch 1
    cudaEventRecord(evFork, 0);
    k_deg<<<(NE + 255) / 256, 256>>>(dst);                    // 2

    // side stream: xconv + prep + conv, concurrent with deg/init1/scatter1
    cudaStreamWaitEvent(s1, evFork, 0);
    k_xconv<<<(NN * 10 + 255) / 256, 256, 0, s1>>>(x);
    cudaEventRecord(evX, s1);
    k_prep<<<(320 * 512 + 255) / 256, 256, 0, s1>>>(W1, W2, fc1_w, fc2_w,
                                                    emb, conv_w);
    cudaEventRecord(evPrep, s1);
    {
        dim3 grid(NG, 2);
        k_conv<<<grid, 256, 0, s1>>>(seq, conv_b);
    }
    cudaEventRecord(evConv, s1);

    cudaStreamWaitEvent(0, evX, 0);                           // init1 needs x16
    k_init1<<<(NE + 255) / 256, 256>>>(batch, src, dst);      // 3
    k_scatter1<<<2048, 256>>>();                              // 4  <- profiled
    cudaStreamWaitEvent(0, evPrep, 0);                        // gemm1 needs w1h
    k_gemm1<<<(NN + 127) / 128, 256>>>(b1);
    k_scatter2<<<2048, 256>>>();
    {
        dim3 grid((NN + 127) / 128, 2);
        k_gemm2<<<grid, 256>>>(b2, batch);
    }
    cudaStreamWaitEvent(0, evConv, 0);                        // gemmf needs prot
    {
        dim3 grid(4, 4);
        k_gemmf<<<grid, 256>>>(fc1_b, out);
    }
}